// round 13
// baseline (speedup 1.0000x reference)
#include <cuda_runtime.h>
#include <cuda_fp16.h>
#include <cstdint>

#define NN 50000
#define EE 800000
#define NBLK 196   // ceil(NN/256)
#define TILES 391  // ceil(NN/128)

// ---------------- device scratch (all-fp16 activation pipeline) ----------------
__device__ __half g_x16[NN * 128];    // x mirror; reused as layer-3 proj p16 [NN*64]
__device__ __half g_hA16[NN * 128];   // layer-1 activations
__device__ __half g_hB16[NN * 128];   // layer-2 activations
__device__ __half g_n16[NN * 128];    // aggregated neighbor features
__device__ float  g_self[NN * 64];    // layer-3 self projection (fp32)
__device__ int   g_deg[NN];
__device__ int   g_off[NN + 1];
__device__ int   g_cur[NN];
__device__ int   g_csr[EE];
__device__ int   g_bsum[256];
__device__ int   g_boff[256];
__device__ int   g_arrive;            // grid-barrier arrival counter
__device__ int   g_gen;              // grid-barrier generation
__device__ __half g_B16[3 * 128 * 256]; // transposed fp16 weights, 3 layers

// ---------------- helpers ----------------
__device__ __forceinline__ uint32_t smem_u32(const void* p) {
    uint32_t a;
    asm("{ .reg .u64 t; cvta.to.shared.u64 t, %1; cvt.u32.u64 %0, t; }" : "=r"(a) : "l"(p));
    return a;
}
__device__ __forceinline__ void mma_f16(float* d, const uint32_t* a, const uint32_t* b) {
    asm volatile(
        "mma.sync.aligned.m16n8k16.row.col.f32.f16.f16.f32 "
        "{%0,%1,%2,%3}, {%4,%5,%6,%7}, {%8,%9}, {%0,%1,%2,%3};"
        : "+f"(d[0]), "+f"(d[1]), "+f"(d[2]), "+f"(d[3])
        : "r"(a[0]), "r"(a[1]), "r"(a[2]), "r"(a[3]), "r"(b[0]), "r"(b[1]));
}
__device__ __forceinline__ void ldsm_x4(uint32_t* r, uint32_t addr) {
    asm volatile("ldmatrix.sync.aligned.m8n8.x4.shared.b16 {%0,%1,%2,%3}, [%4];"
                 : "=r"(r[0]), "=r"(r[1]), "=r"(r[2]), "=r"(r[3]) : "r"(addr));
}

// ---------------- setup: x conv + weight prep + deg zero + barrier reset ----------------
#define NCONV4 (NN * 32)
#define NWPREP (2 * 128 * 256 + 128 * 128)
#define NDEG4  (NN / 4)
__global__ void setup_kernel(const float4* __restrict__ x4, uint2* __restrict__ x16,
                             const float* __restrict__ Ws1, const float* __restrict__ Wn1,
                             const float* __restrict__ Ws2, const float* __restrict__ Wn2,
                             const float* __restrict__ Ws3, const float* __restrict__ Wn3,
                             __half* __restrict__ B16) {
    int idx = blockIdx.x * blockDim.x + threadIdx.x;
    if (idx == 0) { g_arrive = 0; g_gen = 0; }
    if (idx < NCONV4) {
        float4 v = x4[idx];
        __half2 h0 = __floats2half2_rn(v.x, v.y);
        __half2 h1 = __floats2half2_rn(v.z, v.w);
        x16[idx] = make_uint2(*reinterpret_cast<uint32_t*>(&h0), *reinterpret_cast<uint32_t*>(&h1));
        return;
    }
    int w = idx - NCONV4;
    if (w < 2 * 128 * 256) {
        int layer = w >> 15;
        int li = w & 32767;
        int n = li >> 8, k = li & 255;
        const float* W1 = layer ? Ws2 : Ws1;
        const float* W2 = layer ? Wn2 : Wn1;
        float wv = (k < 128) ? W1[k * 128 + n] : W2[(k - 128) * 128 + n];
        B16[w] = __float2half_rn(wv);
    } else if (w < NWPREP) {
        int li = w - 2 * 128 * 256;
        int n = li >> 7, k = li & 127;
        float wv = (n < 64) ? Ws3[k * 64 + n] : Wn3[k * 64 + (n - 64)];
        B16[2 * 128 * 256 + n * 128 + k] = __float2half_rn(wv);
    } else if (w < NWPREP + NDEG4) {
        reinterpret_cast<int4*>(g_deg)[w - NWPREP] = make_int4(0, 0, 0, 0);
    }
}

// ---------------- single cooperative CSR kernel ----------------
// Phases: count -> gsync -> block partial sums -> gsync -> bsum scan (block 0)
//         -> gsync -> offsets + g_cur -> gsync -> fill.
// Grid 782 x 256, 0 smem beyond 1KB, <=32 regs: 6 blocks/SM needed, co-residency guaranteed.
__global__ void __launch_bounds__(256, 8)
csr_kernel(const int4* __restrict__ src4, const int4* __restrict__ dst4) {
    __shared__ int sh[256];
    const int nb = gridDim.x;
    const int tid = threadIdx.x;
    const int bid = blockIdx.x;
    const int gi = bid * 256 + tid;
    int mygen = 0;

    auto gsync = [&]() {
        __syncthreads();
        mygen++;
        if (tid == 0) {
            __threadfence();
            if (atomicAdd(&g_arrive, 1) == nb - 1) {
                g_arrive = 0;
                __threadfence();
                atomicExch(&g_gen, mygen);
            } else {
                while (atomicAdd(&g_gen, 0) < mygen) __nanosleep(64);
            }
        }
        __syncthreads();
    };

    // ---- P0: degree count ----
    if (gi < EE / 4) {
        int4 d = dst4[gi];
        atomicAdd(&g_deg[d.x], 1);
        atomicAdd(&g_deg[d.y], 1);
        atomicAdd(&g_deg[d.z], 1);
        atomicAdd(&g_deg[d.w], 1);
    }
    gsync();

    // ---- P1: per-block partial sums over deg (blocks 0..NBLK-1) ----
    if (bid < NBLK) {
        int i = bid * 256 + tid;
        sh[tid] = (i < NN) ? g_deg[i] : 0;
        __syncthreads();
        for (int o = 128; o > 0; o >>= 1) {
            if (tid < o) sh[tid] += sh[tid + o];
            __syncthreads();
        }
        if (tid == 0) g_bsum[bid] = sh[0];
    }
    gsync();

    // ---- P2: scan block sums (block 0) ----
    if (bid == 0) {
        int v = (tid < NBLK) ? g_bsum[tid] : 0;
        sh[tid] = v;
        __syncthreads();
        for (int o = 1; o < 256; o <<= 1) {
            int x = (tid >= o) ? sh[tid - o] : 0;
            __syncthreads();
            sh[tid] += x;
            __syncthreads();
        }
        if (tid < NBLK) g_boff[tid] = sh[tid] - v;   // exclusive
    }
    gsync();

    // ---- P3: final offsets + cursor init ----
    if (bid < NBLK) {
        int i = bid * 256 + tid;
        int v = (i < NN) ? g_deg[i] : 0;
        sh[tid] = v;
        __syncthreads();
        for (int o = 1; o < 256; o <<= 1) {
            int x = (tid >= o) ? sh[tid - o] : 0;
            __syncthreads();
            sh[tid] += x;
            __syncthreads();
        }
        int off = g_boff[bid] + sh[tid] - v;         // exclusive
        if (i <= NN) g_off[i] = off;
        if (i < NN) g_cur[i] = off;
    }
    gsync();

    // ---- P4: fill CSR ----
    if (gi < EE / 4) {
        int4 d = dst4[gi];
        int4 s = src4[gi];
        int p0 = atomicAdd(&g_cur[d.x], 1);
        int p1 = atomicAdd(&g_cur[d.y], 1);
        int p2 = atomicAdd(&g_cur[d.z], 1);
        int p3 = atomicAdd(&g_cur[d.w], 1);
        g_csr[p0] = s.x;
        g_csr[p1] = s.y;
        g_csr[p2] = s.z;
        g_csr[p3] = s.w;
    }
}

// ---------------- mean aggregation (128-dim): warp per node, fp16 in/out ----------------
__global__ void agg16_kernel(const __half* __restrict__ h16, __half* __restrict__ n16) {
    int gt = blockIdx.x * blockDim.x + threadIdx.x;
    int node = gt >> 5;
    int lane = gt & 31;
    if (node >= NN) return;
    int s = g_off[node], e = g_off[node + 1];
    float a0 = 0.f, a1 = 0.f, a2 = 0.f, a3 = 0.f;
    int j = s;
    for (; j + 4 <= e; j += 4) {
        int i0 = g_csr[j], i1 = g_csr[j + 1], i2 = g_csr[j + 2], i3 = g_csr[j + 3];
        uint2 v0 = *reinterpret_cast<const uint2*>(h16 + (size_t)i0 * 128 + lane * 4);
        uint2 v1 = *reinterpret_cast<const uint2*>(h16 + (size_t)i1 * 128 + lane * 4);
        uint2 v2 = *reinterpret_cast<const uint2*>(h16 + (size_t)i2 * 128 + lane * 4);
        uint2 v3 = *reinterpret_cast<const uint2*>(h16 + (size_t)i3 * 128 + lane * 4);
        float2 f;
        f = __half22float2(*reinterpret_cast<__half2*>(&v0.x)); a0 += f.x; a1 += f.y;
        f = __half22float2(*reinterpret_cast<__half2*>(&v0.y)); a2 += f.x; a3 += f.y;
        f = __half22float2(*reinterpret_cast<__half2*>(&v1.x)); a0 += f.x; a1 += f.y;
        f = __half22float2(*reinterpret_cast<__half2*>(&v1.y)); a2 += f.x; a3 += f.y;
        f = __half22float2(*reinterpret_cast<__half2*>(&v2.x)); a0 += f.x; a1 += f.y;
        f = __half22float2(*reinterpret_cast<__half2*>(&v2.y)); a2 += f.x; a3 += f.y;
        f = __half22float2(*reinterpret_cast<__half2*>(&v3.x)); a0 += f.x; a1 += f.y;
        f = __half22float2(*reinterpret_cast<__half2*>(&v3.y)); a2 += f.x; a3 += f.y;
    }
    for (; j < e; j++) {
        int sidx = g_csr[j];
        uint2 v = *reinterpret_cast<const uint2*>(h16 + (size_t)sidx * 128 + lane * 4);
        float2 f0 = __half22float2(*reinterpret_cast<__half2*>(&v.x));
        float2 f1 = __half22float2(*reinterpret_cast<__half2*>(&v.y));
        a0 += f0.x; a1 += f0.y; a2 += f1.x; a3 += f1.y;
    }
    float inv = 1.0f / (float)max(e - s, 1);
    __half2 o0 = __floats2half2_rn(a0 * inv, a1 * inv);
    __half2 o1 = __floats2half2_rn(a2 * inv, a3 * inv);
    *reinterpret_cast<uint2*>(n16 + (size_t)node * 128 + lane * 4) =
        make_uint2(*reinterpret_cast<uint32_t*>(&o0), *reinterpret_cast<uint32_t*>(&o1));
}

// ---------------- layer-3 final: out = self + mean(proj16[src]) ----------------
__global__ void agg3_kernel(const __half* __restrict__ p16, const float* __restrict__ self,
                            float* __restrict__ out) {
    int gt = blockIdx.x * blockDim.x + threadIdx.x;
    int node = gt >> 5;
    int lane = gt & 31;
    if (node >= NN) return;
    int s = g_off[node], e = g_off[node + 1];
    float a0 = 0.f, a1 = 0.f;
    int j = s;
    for (; j + 4 <= e; j += 4) {
        int i0 = g_csr[j], i1 = g_csr[j + 1], i2 = g_csr[j + 2], i3 = g_csr[j + 3];
        uint32_t v0 = *reinterpret_cast<const uint32_t*>(p16 + (size_t)i0 * 64 + lane * 2);
        uint32_t v1 = *reinterpret_cast<const uint32_t*>(p16 + (size_t)i1 * 64 + lane * 2);
        uint32_t v2 = *reinterpret_cast<const uint32_t*>(p16 + (size_t)i2 * 64 + lane * 2);
        uint32_t v3 = *reinterpret_cast<const uint32_t*>(p16 + (size_t)i3 * 64 + lane * 2);
        float2 f;
        f = __half22float2(*reinterpret_cast<__half2*>(&v0)); a0 += f.x; a1 += f.y;
        f = __half22float2(*reinterpret_cast<__half2*>(&v1)); a0 += f.x; a1 += f.y;
        f = __half22float2(*reinterpret_cast<__half2*>(&v2)); a0 += f.x; a1 += f.y;
        f = __half22float2(*reinterpret_cast<__half2*>(&v3)); a0 += f.x; a1 += f.y;
    }
    for (; j < e; j++) {
        int sidx = g_csr[j];
        uint32_t v = *reinterpret_cast<const uint32_t*>(p16 + (size_t)sidx * 64 + lane * 2);
        float2 f = __half22float2(*reinterpret_cast<__half2*>(&v));
        a0 += f.x; a1 += f.y;
    }
    float inv = 1.0f / (float)max(e - s, 1);
    float2 sv = *reinterpret_cast<const float2*>(self + (size_t)node * 64 + lane * 2);
    *reinterpret_cast<float2*>(out + (size_t)node * 64 + lane * 2) =
        make_float2(sv.x + a0 * inv, sv.y + a1 * inv);
}

// ---------------- single-pass fp16 tensor-core GEMM (fp32 accum), PERSISTENT ----------------
// MODE 0: relu*mask epilogue, fp16 128-wide output (layers 1,2)
// MODE 2: layer-3 split: cols<64 -> self fp32 (+bias), cols>=64 -> p16 fp16 (no bias)
template <int KCHUNKS, bool DUAL, int MODE>
__global__ void __launch_bounds__(256, 2)
sage_mma_kernel(const __half* __restrict__ A0, const __half* __restrict__ A1,
                const __half* __restrict__ B16,
                const float* __restrict__ bias, const float* __restrict__ mask,
                float* __restrict__ out, __half* __restrict__ h16out) {
    constexpr int PAD = 40;                 // halves per smem row (80B: conflict-free ldmatrix)
    constexpr int KTOT = KCHUNKS * 32;
    constexpr int BUFH = 128 * PAD;
    extern __shared__ uint16_t sm[];
    const uint32_t base = smem_u32(sm);
    uint16_t* sA = sm;                      // [2][128][PAD]
    uint16_t* sB = sm + 2 * BUFH;           // [2][128][PAD]

    const int tid = threadIdx.x, lane = tid & 31, wid = tid >> 5;
    const int wm = (wid & 3) * 32;          // 4 warps down M
    const int wn = (wid >> 2) * 64;         // 2 warps across N

    for (int bt = blockIdx.x; bt < TILES; bt += gridDim.x) {
        const int bm = bt * 128;

        float acc[2][8][4];
#pragma unroll
        for (int m = 0; m < 2; m++)
#pragma unroll
            for (int n = 0; n < 8; n++)
#pragma unroll
                for (int i = 0; i < 4; i++) acc[m][n][i] = 0.f;

        uint4 pa[2], pb[2];
        auto loadAB = [&](int ch) {
            const __half* asrc = DUAL ? (ch < KCHUNKS / 2 ? A0 : A1) : A0;
            int klocal = DUAL ? (ch & (KCHUNKS / 2 - 1)) * 32 : ch * 32;
            int k0 = ch * 32;
#pragma unroll
            for (int j = 0; j < 2; j++) {
                int item = tid + j * 256;
                int row = item >> 2, q = item & 3;
                int grow = bm + row;
                pa[j] = (grow < NN)
                    ? *reinterpret_cast<const uint4*>(asrc + (size_t)grow * 128 + klocal + q * 8)
                    : make_uint4(0, 0, 0, 0);
                pb[j] = *reinterpret_cast<const uint4*>(B16 + row * KTOT + k0 + q * 8);
            }
        };
        auto storeAB = [&](int buf) {
#pragma unroll
            for (int j = 0; j < 2; j++) {
                int item = tid + j * 256;
                int row = item >> 2, q = item & 3;
                int off = buf * BUFH + row * PAD + q * 8;
                *reinterpret_cast<uint4*>(&sA[off]) = pa[j];
                *reinterpret_cast<uint4*>(&sB[off]) = pb[j];
            }
        };

        loadAB(0);
        storeAB(0);

        for (int ch = 0; ch < KCHUNKS; ch++) {
            __syncthreads();
            int buf = ch & 1;
            bool more = (ch + 1 < KCHUNKS);
            if (more) loadAB(ch + 1);   // LDGs in flight during MMA work

#pragma unroll
            for (int ks = 0; ks < 2; ks++) {
                uint32_t ah[2][4];
                int arow = wm + (lane & 7) + ((lane >> 3) & 1) * 8;
                int acol = ks * 16 + (lane >> 4) * 8;
#pragma unroll
                for (int m = 0; m < 2; m++) {
                    uint32_t aoff = (uint32_t)(buf * BUFH + (arow + m * 16) * PAD + acol) * 2;
                    ldsm_x4(ah[m], base + aoff);
                }
                int brow = wn + (lane & 7) + ((lane >> 4) & 1) * 8;
                int bcol = ks * 16 + ((lane >> 3) & 1) * 8;
#pragma unroll
                for (int nt2 = 0; nt2 < 4; nt2++) {
                    uint32_t bh[4];
                    uint32_t boff = (uint32_t)((2 + buf) * BUFH + (brow + nt2 * 16) * PAD + bcol) * 2;
                    ldsm_x4(bh, base + boff);
#pragma unroll
                    for (int m = 0; m < 2; m++) {
                        mma_f16(acc[m][nt2 * 2], ah[m], &bh[0]);
                        mma_f16(acc[m][nt2 * 2 + 1], ah[m], &bh[2]);
                    }
                }
            }
            if (more) storeAB(buf ^ 1);
        }

        // ---- epilogue ----
#pragma unroll
        for (int m = 0; m < 2; m++) {
            int r0 = bm + wm + m * 16 + (lane >> 2);
#pragma unroll
            for (int nt = 0; nt < 8; nt++) {
                int c = wn + nt * 8 + (lane & 3) * 2;
#pragma unroll
                for (int hh = 0; hh < 2; hh++) {
                    int r = r0 + hh * 8;
                    if (r >= NN) continue;
                    float v0 = acc[m][nt][hh * 2 + 0];
                    float v1 = acc[m][nt][hh * 2 + 1];
                    if (MODE == 0) {
                        v0 += bias[c];
                        v1 += bias[c + 1];
                        float2 mv = *reinterpret_cast<const float2*>(mask + (size_t)r * 128 + c);
                        v0 = fmaxf(v0, 0.f) * mv.x;
                        v1 = fmaxf(v1, 0.f) * mv.y;
                        *reinterpret_cast<__half2*>(h16out + (size_t)r * 128 + c) =
                            __floats2half2_rn(v0, v1);
                    } else {
                        if (c < 64) {
                            v0 += bias[c];
                            v1 += bias[c + 1];
                            *reinterpret_cast<float2*>(out + (size_t)r * 64 + c) = make_float2(v0, v1);
                        } else {
                            *reinterpret_cast<__half2*>(h16out + (size_t)r * 64 + (c - 64)) =
                                __floats2half2_rn(v0, v1);
                        }
                    }
                }
            }
        }
    }
}

// ---------------- launch ----------------
extern "C" void kernel_launch(void* const* d_in, const int* in_sizes, int n_in,
                              void* d_out, int out_size) {
    const float* x   = (const float*)d_in[0];
    const int*   src = (const int*)d_in[1];
    const int*   dst = (const int*)d_in[2];
    const float* Ws1 = (const float*)d_in[3];
    const float* Wn1 = (const float*)d_in[4];
    const float* b1  = (const float*)d_in[5];
    const float* Ws2 = (const float*)d_in[6];
    const float* Wn2 = (const float*)d_in[7];
    const float* b2  = (const float*)d_in[8];
    const float* Ws3 = (const float*)d_in[9];
    const float* Wn3 = (const float*)d_in[10];
    const float* b3  = (const float*)d_in[11];
    const float* m1  = (const float*)d_in[12];
    const float* m2  = (const float*)d_in[13];
    float* out = (float*)d_out;

    // Real DEVICE addresses (host symbol = ATS shadow trap, see R1)
    __half *x16 = nullptr, *hA16 = nullptr, *hB16 = nullptr, *n16 = nullptr, *B16 = nullptr;
    float* selfp = nullptr;
    cudaGetSymbolAddress((void**)&x16, g_x16);
    cudaGetSymbolAddress((void**)&hA16, g_hA16);
    cudaGetSymbolAddress((void**)&hB16, g_hB16);
    cudaGetSymbolAddress((void**)&n16, g_n16);
    cudaGetSymbolAddress((void**)&B16, g_B16);
    cudaGetSymbolAddress((void**)&selfp, g_self);

    constexpr int SMEM_GEMM = 4 * 128 * 40 * 2;  // 40960 B
    cudaFuncSetAttribute(sage_mma_kernel<8, true, 0>,
                         cudaFuncAttributeMaxDynamicSharedMemorySize, SMEM_GEMM);
    cudaFuncSetAttribute(sage_mma_kernel<4, false, 2>,
                         cudaFuncAttributeMaxDynamicSharedMemorySize, SMEM_GEMM);

    // ---- node 1: setup (conv + weight prep + deg zero + barrier reset) ----
    setup_kernel<<<(NCONV4 + NWPREP + NDEG4 + 255) / 256, 256>>>(
        (const float4*)x, (uint2*)x16, Ws1, Wn1, Ws2, Wn2, Ws3, Wn3, B16);

    // ---- node 2: entire CSR build in ONE cooperative kernel ----
    csr_kernel<<<(EE / 4 + 255) / 256, 256>>>((const int4*)src, (const int4*)dst);

    int aggBlocks = (NN * 32 + 255) / 256;
    int gemmGrid = 296;                  // 2 CTAs/SM x 148 SMs, persistent tile loop

    // ---- layer 1 ----
    agg16_kernel<<<aggBlocks, 256>>>(x16, n16);
    sage_mma_kernel<8, true, 0><<<gemmGrid, 256, SMEM_GEMM>>>(x16, n16, B16, b1, m1, nullptr, hA16);

    // ---- layer 2 ----
    agg16_kernel<<<aggBlocks, 256>>>(hA16, n16);
    sage_mma_kernel<8, true, 0><<<gemmGrid, 256, SMEM_GEMM>>>(hA16, n16, B16 + 32768, b2, m2, nullptr, hB16);

    // ---- layer 3: project (self fp32, proj fp16 into x16), then aggregate ----
    sage_mma_kernel<4, false, 2><<<gemmGrid, 256, SMEM_GEMM>>>(hB16, nullptr, B16 + 65536, b3, nullptr, selfp, x16);
    agg3_kernel<<<aggBlocks, 256>>>(x16, selfp, out);
}

// round 14
// speedup vs baseline: 1.0056x; 1.0056x over previous
#include <cuda_runtime.h>
#include <cuda_fp16.h>
#include <cstdint>

#define NN 50000
#define EE 800000
#define NBLK 196   // ceil(NN/256)
#define TILES 391  // ceil(NN/128)

// ---------------- device scratch (all-fp16 activation pipeline) ----------------
__device__ __half g_x16[NN * 128];    // x mirror; reused as layer-3 proj p16 [NN*64]
__device__ __half g_hA16[NN * 128];   // layer-1 activations
__device__ __half g_hB16[NN * 128];   // layer-2 activations
__device__ __half g_n16[NN * 128];    // aggregated neighbor features
__device__ float  g_self[NN * 64];    // layer-3 self projection (fp32)
__device__ int   g_deg[NN];
__device__ int   g_off[NN + 1];
__device__ int   g_cur[NN];
__device__ int   g_csr[EE];
__device__ int   g_bsum[256];
__device__ int   g_boff[256];
__device__ int   g_scanctr;
__device__ __half g_B16[3 * 128 * 256]; // transposed fp16 weights, 3 layers

// ---------------- helpers ----------------
__device__ __forceinline__ uint32_t smem_u32(const void* p) {
    uint32_t a;
    asm("{ .reg .u64 t; cvta.to.shared.u64 t, %1; cvt.u32.u64 %0, t; }" : "=r"(a) : "l"(p));
    return a;
}
__device__ __forceinline__ void mma_f16(float* d, const uint32_t* a, const uint32_t* b) {
    asm volatile(
        "mma.sync.aligned.m16n8k16.row.col.f32.f16.f16.f32 "
        "{%0,%1,%2,%3}, {%4,%5,%6,%7}, {%8,%9}, {%0,%1,%2,%3};"
        : "+f"(d[0]), "+f"(d[1]), "+f"(d[2]), "+f"(d[3])
        : "r"(a[0]), "r"(a[1]), "r"(a[2]), "r"(a[3]), "r"(b[0]), "r"(b[1]));
}
__device__ __forceinline__ void ldsm_x4(uint32_t* r, uint32_t addr) {
    asm volatile("ldmatrix.sync.aligned.m8n8.x4.shared.b16 {%0,%1,%2,%3}, [%4];"
                 : "=r"(r[0]), "=r"(r[1]), "=r"(r[2]), "=r"(r[3]) : "r"(addr));
}

// ---------------- setup: x conv + weight prep + deg zero ----------------
#define NCONV4 (NN * 32)
#define NWPREP (2 * 128 * 256 + 128 * 128)
#define NDEG4  (NN / 4)
__global__ void setup_kernel(const float4* __restrict__ x4, uint2* __restrict__ x16,
                             const float* __restrict__ Ws1, const float* __restrict__ Wn1,
                             const float* __restrict__ Ws2, const float* __restrict__ Wn2,
                             const float* __restrict__ Ws3, const float* __restrict__ Wn3,
                             __half* __restrict__ B16) {
    int idx = blockIdx.x * blockDim.x + threadIdx.x;
    if (idx < NCONV4) {
        float4 v = x4[idx];
        __half2 h0 = __floats2half2_rn(v.x, v.y);
        __half2 h1 = __floats2half2_rn(v.z, v.w);
        x16[idx] = make_uint2(*reinterpret_cast<uint32_t*>(&h0), *reinterpret_cast<uint32_t*>(&h1));
        return;
    }
    int w = idx - NCONV4;
    if (w < 2 * 128 * 256) {
        int layer = w >> 15;
        int li = w & 32767;
        int n = li >> 8, k = li & 255;
        const float* W1 = layer ? Ws2 : Ws1;
        const float* W2 = layer ? Wn2 : Wn1;
        float wv = (k < 128) ? W1[k * 128 + n] : W2[(k - 128) * 128 + n];
        B16[w] = __float2half_rn(wv);
    } else if (w < NWPREP) {
        int li = w - 2 * 128 * 256;
        int n = li >> 7, k = li & 127;
        float wv = (n < 64) ? Ws3[k * 64 + n] : Wn3[k * 64 + (n - 64)];
        B16[2 * 128 * 256 + n * 128 + k] = __float2half_rn(wv);
    } else if (w < NWPREP + NDEG4) {
        reinterpret_cast<int4*>(g_deg)[w - NWPREP] = make_int4(0, 0, 0, 0);
    }
}

// ---------------- CSR build (validated 5-node chain) ----------------
__global__ void count4_kernel(const int4* __restrict__ dst4) {
    int i = blockIdx.x * blockDim.x + threadIdx.x;
    if (i == 0) g_scanctr = 0;
    if (i < EE / 4) {
        int4 d = dst4[i];
        atomicAdd(&g_deg[d.x], 1);
        atomicAdd(&g_deg[d.y], 1);
        atomicAdd(&g_deg[d.z], 1);
        atomicAdd(&g_deg[d.w], 1);
    }
}
__global__ void scan12_kernel() {
    __shared__ int sh[256];
    __shared__ int lastflag;
    int t = threadIdx.x;
    int i = blockIdx.x * 256 + t;
    sh[t] = (i < NN) ? g_deg[i] : 0;
    __syncthreads();
    for (int o = 128; o > 0; o >>= 1) {
        if (t < o) sh[t] += sh[t + o];
        __syncthreads();
    }
    if (t == 0) {
        g_bsum[blockIdx.x] = sh[0];
        __threadfence();
        lastflag = (atomicAdd(&g_scanctr, 1) == NBLK - 1);
    }
    __syncthreads();
    if (lastflag) {
        int v = (t < NBLK) ? g_bsum[t] : 0;
        sh[t] = v;
        __syncthreads();
        for (int o = 1; o < 256; o <<= 1) {
            int x = (t >= o) ? sh[t - o] : 0;
            __syncthreads();
            sh[t] += x;
            __syncthreads();
        }
        if (t < NBLK) g_boff[t] = sh[t] - v;   // exclusive
    }
}
__global__ void scan_final() {
    __shared__ int sh[256];
    int t = threadIdx.x;
    int i = blockIdx.x * 256 + t;
    int v = (i < NN) ? g_deg[i] : 0;
    sh[t] = v;
    __syncthreads();
    for (int o = 1; o < 256; o <<= 1) {
        int x = (t >= o) ? sh[t - o] : 0;
        __syncthreads();
        sh[t] += x;
        __syncthreads();
    }
    int off = g_boff[blockIdx.x] + sh[t] - v;   // exclusive
    if (i <= NN) g_off[i] = off;
    if (i < NN) g_cur[i] = off;
}
__global__ void fill4_kernel(const int4* __restrict__ src4, const int4* __restrict__ dst4) {
    int i = blockIdx.x * blockDim.x + threadIdx.x;
    if (i < EE / 4) {
        int4 d = dst4[i];
        int4 s = src4[i];
        int p0 = atomicAdd(&g_cur[d.x], 1);
        int p1 = atomicAdd(&g_cur[d.y], 1);
        int p2 = atomicAdd(&g_cur[d.z], 1);
        int p3 = atomicAdd(&g_cur[d.w], 1);
        g_csr[p0] = s.x;
        g_csr[p1] = s.y;
        g_csr[p2] = s.z;
        g_csr[p3] = s.w;
    }
}

// ---------------- mean aggregation (128-dim): warp per node, fp16 in/out ----------------
__global__ void agg16_kernel(const __half* __restrict__ h16, __half* __restrict__ n16) {
    int gt = blockIdx.x * blockDim.x + threadIdx.x;
    int node = gt >> 5;
    int lane = gt & 31;
    if (node >= NN) return;
    int s = g_off[node], e = g_off[node + 1];
    float a0 = 0.f, a1 = 0.f, a2 = 0.f, a3 = 0.f;
    int j = s;
    for (; j + 4 <= e; j += 4) {
        int i0 = g_csr[j], i1 = g_csr[j + 1], i2 = g_csr[j + 2], i3 = g_csr[j + 3];
        uint2 v0 = *reinterpret_cast<const uint2*>(h16 + (size_t)i0 * 128 + lane * 4);
        uint2 v1 = *reinterpret_cast<const uint2*>(h16 + (size_t)i1 * 128 + lane * 4);
        uint2 v2 = *reinterpret_cast<const uint2*>(h16 + (size_t)i2 * 128 + lane * 4);
        uint2 v3 = *reinterpret_cast<const uint2*>(h16 + (size_t)i3 * 128 + lane * 4);
        float2 f;
        f = __half22float2(*reinterpret_cast<__half2*>(&v0.x)); a0 += f.x; a1 += f.y;
        f = __half22float2(*reinterpret_cast<__half2*>(&v0.y)); a2 += f.x; a3 += f.y;
        f = __half22float2(*reinterpret_cast<__half2*>(&v1.x)); a0 += f.x; a1 += f.y;
        f = __half22float2(*reinterpret_cast<__half2*>(&v1.y)); a2 += f.x; a3 += f.y;
        f = __half22float2(*reinterpret_cast<__half2*>(&v2.x)); a0 += f.x; a1 += f.y;
        f = __half22float2(*reinterpret_cast<__half2*>(&v2.y)); a2 += f.x; a3 += f.y;
        f = __half22float2(*reinterpret_cast<__half2*>(&v3.x)); a0 += f.x; a1 += f.y;
        f = __half22float2(*reinterpret_cast<__half2*>(&v3.y)); a2 += f.x; a3 += f.y;
    }
    for (; j < e; j++) {
        int sidx = g_csr[j];
        uint2 v = *reinterpret_cast<const uint2*>(h16 + (size_t)sidx * 128 + lane * 4);
        float2 f0 = __half22float2(*reinterpret_cast<__half2*>(&v.x));
        float2 f1 = __half22float2(*reinterpret_cast<__half2*>(&v.y));
        a0 += f0.x; a1 += f0.y; a2 += f1.x; a3 += f1.y;
    }
    float inv = 1.0f / (float)max(e - s, 1);
    __half2 o0 = __floats2half2_rn(a0 * inv, a1 * inv);
    __half2 o1 = __floats2half2_rn(a2 * inv, a3 * inv);
    *reinterpret_cast<uint2*>(n16 + (size_t)node * 128 + lane * 4) =
        make_uint2(*reinterpret_cast<uint32_t*>(&o0), *reinterpret_cast<uint32_t*>(&o1));
}

// ---------------- layer-3 final: out = self + mean(proj16[src]) ----------------
__global__ void agg3_kernel(const __half* __restrict__ p16, const float* __restrict__ self,
                            float* __restrict__ out) {
    int gt = blockIdx.x * blockDim.x + threadIdx.x;
    int node = gt >> 5;
    int lane = gt & 31;
    if (node >= NN) return;
    int s = g_off[node], e = g_off[node + 1];
    float a0 = 0.f, a1 = 0.f;
    int j = s;
    for (; j + 4 <= e; j += 4) {
        int i0 = g_csr[j], i1 = g_csr[j + 1], i2 = g_csr[j + 2], i3 = g_csr[j + 3];
        uint32_t v0 = *reinterpret_cast<const uint32_t*>(p16 + (size_t)i0 * 64 + lane * 2);
        uint32_t v1 = *reinterpret_cast<const uint32_t*>(p16 + (size_t)i1 * 64 + lane * 2);
        uint32_t v2 = *reinterpret_cast<const uint32_t*>(p16 + (size_t)i2 * 64 + lane * 2);
        uint32_t v3 = *reinterpret_cast<const uint32_t*>(p16 + (size_t)i3 * 64 + lane * 2);
        float2 f;
        f = __half22float2(*reinterpret_cast<__half2*>(&v0)); a0 += f.x; a1 += f.y;
        f = __half22float2(*reinterpret_cast<__half2*>(&v1)); a0 += f.x; a1 += f.y;
        f = __half22float2(*reinterpret_cast<__half2*>(&v2)); a0 += f.x; a1 += f.y;
        f = __half22float2(*reinterpret_cast<__half2*>(&v3)); a0 += f.x; a1 += f.y;
    }
    for (; j < e; j++) {
        int sidx = g_csr[j];
        uint32_t v = *reinterpret_cast<const uint32_t*>(p16 + (size_t)sidx * 64 + lane * 2);
        float2 f = __half22float2(*reinterpret_cast<__half2*>(&v));
        a0 += f.x; a1 += f.y;
    }
    float inv = 1.0f / (float)max(e - s, 1);
    float2 sv = *reinterpret_cast<const float2*>(self + (size_t)node * 64 + lane * 2);
    *reinterpret_cast<float2*>(out + (size_t)node * 64 + lane * 2) =
        make_float2(sv.x + a0 * inv, sv.y + a1 * inv);
}

// ---------------- persistent fp16 GEMM with B RESIDENT in SMEM ----------------
// B loaded once per CTA into [128][KTOT+8] (row stride 16B-aligned, conflict-free ldsm),
// reused across all tiles. Per tile only A is staged (double-buffered).
// MODE 0: relu*mask epilogue, fp16 128-wide output (layers 1,2)
// MODE 2: layer-3 split: cols<64 -> self fp32 (+bias), cols>=64 -> p16 fp16 (no bias)
template <int KTOT, bool DUAL, int MODE>
__global__ void __launch_bounds__(256, 2)
sage_mma_kernel(const __half* __restrict__ A0, const __half* __restrict__ A1,
                const __half* __restrict__ B16,
                const float* __restrict__ bias, const float* __restrict__ mask,
                float* __restrict__ out, __half* __restrict__ h16out) {
    constexpr int KCHUNKS = KTOT / 32;
    constexpr int PAD = 40;                 // A row stride (halves)
    constexpr int BUFH = 128 * PAD;         // halves per A buffer
    constexpr int PADB = KTOT + 8;          // B row stride (halves): 16B-aligned, bank-clean
    extern __shared__ uint16_t sm[];
    uint16_t* sA = sm;                      // [2][128][PAD]
    uint16_t* sB = sm + 2 * BUFH;           // [128][PADB]
    const uint32_t base = smem_u32(sm);
    const uint32_t baseB = base + (uint32_t)(2 * BUFH) * 2;

    const int tid = threadIdx.x, lane = tid & 31, wid = tid >> 5;
    const int wm = (wid & 3) * 32;          // 4 warps down M
    const int wn = (wid >> 2) * 64;         // 2 warps across N

    // ---- load B once (resident) ----
    for (int i = tid; i < 128 * (KTOT / 8); i += 256) {
        int row = i / (KTOT / 8), q = i % (KTOT / 8);
        *reinterpret_cast<uint4*>(&sB[row * PADB + q * 8]) =
            *reinterpret_cast<const uint4*>(B16 + row * KTOT + q * 8);
    }
    // first __syncthreads inside the chunk loop fences this before any B ldsm.

    for (int bt = blockIdx.x; bt < TILES; bt += gridDim.x) {
        const int bm = bt * 128;

        float acc[2][8][4];
#pragma unroll
        for (int m = 0; m < 2; m++)
#pragma unroll
            for (int n = 0; n < 8; n++)
#pragma unroll
                for (int i = 0; i < 4; i++) acc[m][n][i] = 0.f;

        uint4 pa[2];
        auto loadA = [&](int ch) {
            const __half* asrc = DUAL ? (ch < KCHUNKS / 2 ? A0 : A1) : A0;
            int klocal = DUAL ? (ch & (KCHUNKS / 2 - 1)) * 32 : ch * 32;
#pragma unroll
            for (int j = 0; j < 2; j++) {
                int item = tid + j * 256;
                int row = item >> 2, q = item & 3;
                int grow = bm + row;
                pa[j] = (grow < NN)
                    ? *reinterpret_cast<const uint4*>(asrc + (size_t)grow * 128 + klocal + q * 8)
                    : make_uint4(0, 0, 0, 0);
            }
        };
        auto storeA = [&](int buf) {
#pragma unroll
            for (int j = 0; j < 2; j++) {
                int item = tid + j * 256;
                int row = item >> 2, q = item & 3;
                *reinterpret_cast<uint4*>(&sA[buf * BUFH + row * PAD + q * 8]) = pa[j];
            }
        };

        loadA(0);
        storeA(0);

        for (int ch = 0; ch < KCHUNKS; ch++) {
            __syncthreads();
            int buf = ch & 1;
            bool more = (ch + 1 < KCHUNKS);
            if (more) loadA(ch + 1);

#pragma unroll
            for (int ks = 0; ks < 2; ks++) {
                uint32_t ah[2][4];
                int arow = wm + (lane & 7) + ((lane >> 3) & 1) * 8;
                int acol = ks * 16 + (lane >> 4) * 8;
#pragma unroll
                for (int m = 0; m < 2; m++) {
                    uint32_t aoff = (uint32_t)(buf * BUFH + (arow + m * 16) * PAD + acol) * 2;
                    ldsm_x4(ah[m], base + aoff);
                }
                int brow = wn + (lane & 7) + ((lane >> 4) & 1) * 8;
                int bcol = ch * 32 + ks * 16 + ((lane >> 3) & 1) * 8;
#pragma unroll
                for (int nt2 = 0; nt2 < 4; nt2++) {
                    uint32_t bh[4];
                    uint32_t boff = (uint32_t)((brow + nt2 * 16) * PADB + bcol) * 2;
                    ldsm_x4(bh, baseB + boff);
#pragma unroll
                    for (int m = 0; m < 2; m++) {
                        mma_f16(acc[m][nt2 * 2], ah[m], &bh[0]);
                        mma_f16(acc[m][nt2 * 2 + 1], ah[m], &bh[2]);
                    }
                }
            }
            if (more) storeA(buf ^ 1);
        }

        // ---- epilogue ----
#pragma unroll
        for (int m = 0; m < 2; m++) {
            int r0 = bm + wm + m * 16 + (lane >> 2);
#pragma unroll
            for (int nt = 0; nt < 8; nt++) {
                int c = wn + nt * 8 + (lane & 3) * 2;
#pragma unroll
                for (int hh = 0; hh < 2; hh++) {
                    int r = r0 + hh * 8;
                    if (r >= NN) continue;
                    float v0 = acc[m][nt][hh * 2 + 0];
                    float v1 = acc[m][nt][hh * 2 + 1];
                    if (MODE == 0) {
                        v0 += bias[c];
                        v1 += bias[c + 1];
                        float2 mv = *reinterpret_cast<const float2*>(mask + (size_t)r * 128 + c);
                        v0 = fmaxf(v0, 0.f) * mv.x;
                        v1 = fmaxf(v1, 0.f) * mv.y;
                        *reinterpret_cast<__half2*>(h16out + (size_t)r * 128 + c) =
                            __floats2half2_rn(v0, v1);
                    } else {
                        if (c < 64) {
                            v0 += bias[c];
                            v1 += bias[c + 1];
                            *reinterpret_cast<float2*>(out + (size_t)r * 64 + c) = make_float2(v0, v1);
                        } else {
                            *reinterpret_cast<__half2*>(h16out + (size_t)r * 64 + (c - 64)) =
                                __floats2half2_rn(v0, v1);
                        }
                    }
                }
            }
        }
        // next tile's storeA(0) touches buf0 only; last buf0 reads were fenced
        // by the __syncthreads at the top of the final chunk. B is read-only.
    }
}

// ---------------- launch ----------------
extern "C" void kernel_launch(void* const* d_in, const int* in_sizes, int n_in,
                              void* d_out, int out_size) {
    const float* x   = (const float*)d_in[0];
    const int*   src = (const int*)d_in[1];
    const int*   dst = (const int*)d_in[2];
    const float* Ws1 = (const float*)d_in[3];
    const float* Wn1 = (const float*)d_in[4];
    const float* b1  = (const float*)d_in[5];
    const float* Ws2 = (const float*)d_in[6];
    const float* Wn2 = (const float*)d_in[7];
    const float* b2  = (const float*)d_in[8];
    const float* Ws3 = (const float*)d_in[9];
    const float* Wn3 = (const float*)d_in[10];
    const float* b3  = (const float*)d_in[11];
    const float* m1  = (const float*)d_in[12];
    const float* m2  = (const float*)d_in[13];
    float* out = (float*)d_out;

    // Real DEVICE addresses (host symbol = ATS shadow trap, see R1)
    __half *x16 = nullptr, *hA16 = nullptr, *hB16 = nullptr, *n16 = nullptr, *B16 = nullptr;
    float* selfp = nullptr;
    cudaGetSymbolAddress((void**)&x16, g_x16);
    cudaGetSymbolAddress((void**)&hA16, g_hA16);
    cudaGetSymbolAddress((void**)&hB16, g_hB16);
    cudaGetSymbolAddress((void**)&n16, g_n16);
    cudaGetSymbolAddress((void**)&B16, g_B16);
    cudaGetSymbolAddress((void**)&selfp, g_self);

    constexpr int SMEM_L12 = 2 * 128 * 40 * 2 + 128 * (256 + 8) * 2;  // 88064 B
    constexpr int SMEM_L3  = 2 * 128 * 40 * 2 + 128 * (128 + 8) * 2;  // 55296 B
    cudaFuncSetAttribute(sage_mma_kernel<256, true, 0>,
                         cudaFuncAttributeMaxDynamicSharedMemorySize, SMEM_L12);
    cudaFuncSetAttribute(sage_mma_kernel<128, false, 2>,
                         cudaFuncAttributeMaxDynamicSharedMemorySize, SMEM_L3);

    // ---- setup (conv + weight prep + deg zero) ----
    setup_kernel<<<(NCONV4 + NWPREP + NDEG4 + 255) / 256, 256>>>(
        (const float4*)x, (uint2*)x16, Ws1, Wn1, Ws2, Wn2, Ws3, Wn3, B16);

    // ---- CSR build (validated chain) ----
    count4_kernel<<<(EE / 4 + 255) / 256, 256>>>((const int4*)dst);
    scan12_kernel<<<NBLK, 256>>>();
    scan_final<<<NBLK, 256>>>();
    fill4_kernel<<<(EE / 4 + 255) / 256, 256>>>((const int4*)src, (const int4*)dst);

    int aggBlocks = (NN * 32 + 255) / 256;
    int gemmGrid = 296;                  // 2 CTAs/SM x 148 SMs, persistent tiles

    // ---- layer 1 ----
    agg16_kernel<<<aggBlocks, 256>>>(x16, n16);
    sage_mma_kernel<256, true, 0><<<gemmGrid, 256, SMEM_L12>>>(x16, n16, B16, b1, m1, nullptr, hA16);

    // ---- layer 2 ----
    agg16_kernel<<<aggBlocks, 256>>>(hA16, n16);
    sage_mma_kernel<256, true, 0><<<gemmGrid, 256, SMEM_L12>>>(hA16, n16, B16 + 32768, b2, m2, nullptr, hB16);

    // ---- layer 3: project (self fp32, proj fp16 into x16), then aggregate ----
    sage_mma_kernel<128, false, 2><<<gemmGrid, 256, SMEM_L3>>>(hB16, nullptr, B16 + 65536, b3, nullptr, selfp, x16);
    agg3_kernel<<<aggBlocks, 256>>>(x16, selfp, out);
}

// round 15
// speedup vs baseline: 1.0319x; 1.0262x over previous
#include <cuda_runtime.h>
#include <cuda_fp16.h>
#include <cstdint>

#define NN 50000
#define EE 800000
#define NBLK 196   // ceil(NN/256)
#define TILES 391  // ceil(NN/128)

// ---------------- device scratch (all-fp16 activation pipeline) ----------------
__device__ __half g_x16[NN * 128];    // x mirror; reused as layer-3 proj p16 [NN*64]
__device__ __half g_hA16[NN * 128];   // layer-1 activations
__device__ __half g_hB16[NN * 128];   // layer-2 activations
__device__ __half g_n16[NN * 128];    // aggregated neighbor features
__device__ float  g_self[NN * 64];    // layer-3 self projection (fp32)
__device__ int   g_deg[NN];
__device__ int   g_off[NN + 1];
__device__ int   g_cur[NN];
__device__ int   g_csr[EE];
__device__ int   g_bsum[256];
__device__ int   g_boff[256];
__device__ int   g_scanctr;
__device__ __half g_B16[3 * 128 * 256]; // transposed fp16 weights, 3 layers

// ---------------- helpers ----------------
__device__ __forceinline__ uint32_t smem_u32(const void* p) {
    uint32_t a;
    asm("{ .reg .u64 t; cvta.to.shared.u64 t, %1; cvt.u32.u64 %0, t; }" : "=r"(a) : "l"(p));
    return a;
}
__device__ __forceinline__ void mma_f16(float* d, const uint32_t* a, const uint32_t* b) {
    asm volatile(
        "mma.sync.aligned.m16n8k16.row.col.f32.f16.f16.f32 "
        "{%0,%1,%2,%3}, {%4,%5,%6,%7}, {%8,%9}, {%0,%1,%2,%3};"
        : "+f"(d[0]), "+f"(d[1]), "+f"(d[2]), "+f"(d[3])
        : "r"(a[0]), "r"(a[1]), "r"(a[2]), "r"(a[3]), "r"(b[0]), "r"(b[1]));
}
__device__ __forceinline__ void ldsm_x4(uint32_t* r, uint32_t addr) {
    asm volatile("ldmatrix.sync.aligned.m8n8.x4.shared.b16 {%0,%1,%2,%3}, [%4];"
                 : "=r"(r[0]), "=r"(r[1]), "=r"(r[2]), "=r"(r[3]) : "r"(addr));
}

// ---------------- setup: x conv + weight prep + deg zero ----------------
#define NCONV4 (NN * 32)
#define NWPREP (2 * 128 * 256 + 128 * 128)
#define NDEG4  (NN / 4)
__global__ void setup_kernel(const float4* __restrict__ x4, uint2* __restrict__ x16,
                             const float* __restrict__ Ws1, const float* __restrict__ Wn1,
                             const float* __restrict__ Ws2, const float* __restrict__ Wn2,
                             const float* __restrict__ Ws3, const float* __restrict__ Wn3,
                             __half* __restrict__ B16) {
    int idx = blockIdx.x * blockDim.x + threadIdx.x;
    if (idx < NCONV4) {
        float4 v = x4[idx];
        __half2 h0 = __floats2half2_rn(v.x, v.y);
        __half2 h1 = __floats2half2_rn(v.z, v.w);
        x16[idx] = make_uint2(*reinterpret_cast<uint32_t*>(&h0), *reinterpret_cast<uint32_t*>(&h1));
        return;
    }
    int w = idx - NCONV4;
    if (w < 2 * 128 * 256) {
        int layer = w >> 15;
        int li = w & 32767;
        int n = li >> 8, k = li & 255;
        const float* W1 = layer ? Ws2 : Ws1;
        const float* W2 = layer ? Wn2 : Wn1;
        float wv = (k < 128) ? W1[k * 128 + n] : W2[(k - 128) * 128 + n];
        B16[w] = __float2half_rn(wv);
    } else if (w < NWPREP) {
        int li = w - 2 * 128 * 256;
        int n = li >> 7, k = li & 127;
        float wv = (n < 64) ? Ws3[k * 64 + n] : Wn3[k * 64 + (n - 64)];
        B16[2 * 128 * 256 + n * 128 + k] = __float2half_rn(wv);
    } else if (w < NWPREP + NDEG4) {
        reinterpret_cast<int4*>(g_deg)[w - NWPREP] = make_int4(0, 0, 0, 0);
    }
}

// ---------------- CSR build ----------------
__global__ void count4_kernel(const int4* __restrict__ dst4) {
    int i = blockIdx.x * blockDim.x + threadIdx.x;
    if (i == 0) g_scanctr = 0;
    if (i < EE / 4) {
        int4 d = dst4[i];
        atomicAdd(&g_deg[d.x], 1);
        atomicAdd(&g_deg[d.y], 1);
        atomicAdd(&g_deg[d.z], 1);
        atomicAdd(&g_deg[d.w], 1);
    }
}
__global__ void scan12_kernel() {
    __shared__ int sh[256];
    __shared__ int lastflag;
    int t = threadIdx.x;
    int i = blockIdx.x * 256 + t;
    sh[t] = (i < NN) ? g_deg[i] : 0;
    __syncthreads();
    for (int o = 128; o > 0; o >>= 1) {
        if (t < o) sh[t] += sh[t + o];
        __syncthreads();
    }
    if (t == 0) {
        g_bsum[blockIdx.x] = sh[0];
        __threadfence();
        lastflag = (atomicAdd(&g_scanctr, 1) == NBLK - 1);
    }
    __syncthreads();
    if (lastflag) {
        int v = (t < NBLK) ? g_bsum[t] : 0;
        sh[t] = v;
        __syncthreads();
        for (int o = 1; o < 256; o <<= 1) {
            int x = (t >= o) ? sh[t - o] : 0;
            __syncthreads();
            sh[t] += x;
            __syncthreads();
        }
        if (t < NBLK) g_boff[t] = sh[t] - v;   // exclusive
    }
}
__global__ void scan_final() {
    __shared__ int sh[256];
    int t = threadIdx.x;
    int i = blockIdx.x * 256 + t;
    int v = (i < NN) ? g_deg[i] : 0;
    sh[t] = v;
    __syncthreads();
    for (int o = 1; o < 256; o <<= 1) {
        int x = (t >= o) ? sh[t - o] : 0;
        __syncthreads();
        sh[t] += x;
        __syncthreads();
    }
    int off = g_boff[blockIdx.x] + sh[t] - v;   // exclusive
    if (i <= NN) g_off[i] = off;
    if (i < NN) g_cur[i] = off;
}
__global__ void fill4_kernel(const int4* __restrict__ src4, const int4* __restrict__ dst4) {
    int i = blockIdx.x * blockDim.x + threadIdx.x;
    if (i < EE / 4) {
        int4 d = dst4[i];
        int4 s = src4[i];
        int p0 = atomicAdd(&g_cur[d.x], 1);
        int p1 = atomicAdd(&g_cur[d.y], 1);
        int p2 = atomicAdd(&g_cur[d.z], 1);
        int p3 = atomicAdd(&g_cur[d.w], 1);
        g_csr[p0] = s.x;
        g_csr[p1] = s.y;
        g_csr[p2] = s.z;
        g_csr[p3] = s.w;
    }
}

// ---------------- mean aggregation (128-dim): warp per node, fp16 in/out ----------------
__global__ void agg16_kernel(const __half* __restrict__ h16, __half* __restrict__ n16) {
    int gt = blockIdx.x * blockDim.x + threadIdx.x;
    int node = gt >> 5;
    int lane = gt & 31;
    if (node >= NN) return;
    int s = g_off[node], e = g_off[node + 1];
    float a0 = 0.f, a1 = 0.f, a2 = 0.f, a3 = 0.f;
    int j = s;
    for (; j + 4 <= e; j += 4) {
        int i0 = g_csr[j], i1 = g_csr[j + 1], i2 = g_csr[j + 2], i3 = g_csr[j + 3];
        uint2 v0 = *reinterpret_cast<const uint2*>(h16 + (size_t)i0 * 128 + lane * 4);
        uint2 v1 = *reinterpret_cast<const uint2*>(h16 + (size_t)i1 * 128 + lane * 4);
        uint2 v2 = *reinterpret_cast<const uint2*>(h16 + (size_t)i2 * 128 + lane * 4);
        uint2 v3 = *reinterpret_cast<const uint2*>(h16 + (size_t)i3 * 128 + lane * 4);
        float2 f;
        f = __half22float2(*reinterpret_cast<__half2*>(&v0.x)); a0 += f.x; a1 += f.y;
        f = __half22float2(*reinterpret_cast<__half2*>(&v0.y)); a2 += f.x; a3 += f.y;
        f = __half22float2(*reinterpret_cast<__half2*>(&v1.x)); a0 += f.x; a1 += f.y;
        f = __half22float2(*reinterpret_cast<__half2*>(&v1.y)); a2 += f.x; a3 += f.y;
        f = __half22float2(*reinterpret_cast<__half2*>(&v2.x)); a0 += f.x; a1 += f.y;
        f = __half22float2(*reinterpret_cast<__half2*>(&v2.y)); a2 += f.x; a3 += f.y;
        f = __half22float2(*reinterpret_cast<__half2*>(&v3.x)); a0 += f.x; a1 += f.y;
        f = __half22float2(*reinterpret_cast<__half2*>(&v3.y)); a2 += f.x; a3 += f.y;
    }
    for (; j < e; j++) {
        int sidx = g_csr[j];
        uint2 v = *reinterpret_cast<const uint2*>(h16 + (size_t)sidx * 128 + lane * 4);
        float2 f0 = __half22float2(*reinterpret_cast<__half2*>(&v.x));
        float2 f1 = __half22float2(*reinterpret_cast<__half2*>(&v.y));
        a0 += f0.x; a1 += f0.y; a2 += f1.x; a3 += f1.y;
    }
    float inv = 1.0f / (float)max(e - s, 1);
    __half2 o0 = __floats2half2_rn(a0 * inv, a1 * inv);
    __half2 o1 = __floats2half2_rn(a2 * inv, a3 * inv);
    *reinterpret_cast<uint2*>(n16 + (size_t)node * 128 + lane * 4) =
        make_uint2(*reinterpret_cast<uint32_t*>(&o0), *reinterpret_cast<uint32_t*>(&o1));
}

// ---------------- layer-3 final: out = self + mean(proj16[src]) ----------------
__global__ void agg3_kernel(const __half* __restrict__ p16, const float* __restrict__ self,
                            float* __restrict__ out) {
    int gt = blockIdx.x * blockDim.x + threadIdx.x;
    int node = gt >> 5;
    int lane = gt & 31;
    if (node >= NN) return;
    int s = g_off[node], e = g_off[node + 1];
    float a0 = 0.f, a1 = 0.f;
    int j = s;
    for (; j + 4 <= e; j += 4) {
        int i0 = g_csr[j], i1 = g_csr[j + 1], i2 = g_csr[j + 2], i3 = g_csr[j + 3];
        uint32_t v0 = *reinterpret_cast<const uint32_t*>(p16 + (size_t)i0 * 64 + lane * 2);
        uint32_t v1 = *reinterpret_cast<const uint32_t*>(p16 + (size_t)i1 * 64 + lane * 2);
        uint32_t v2 = *reinterpret_cast<const uint32_t*>(p16 + (size_t)i2 * 64 + lane * 2);
        uint32_t v3 = *reinterpret_cast<const uint32_t*>(p16 + (size_t)i3 * 64 + lane * 2);
        float2 f;
        f = __half22float2(*reinterpret_cast<__half2*>(&v0)); a0 += f.x; a1 += f.y;
        f = __half22float2(*reinterpret_cast<__half2*>(&v1)); a0 += f.x; a1 += f.y;
        f = __half22float2(*reinterpret_cast<__half2*>(&v2)); a0 += f.x; a1 += f.y;
        f = __half22float2(*reinterpret_cast<__half2*>(&v3)); a0 += f.x; a1 += f.y;
    }
    for (; j < e; j++) {
        int sidx = g_csr[j];
        uint32_t v = *reinterpret_cast<const uint32_t*>(p16 + (size_t)sidx * 64 + lane * 2);
        float2 f = __half22float2(*reinterpret_cast<__half2*>(&v));
        a0 += f.x; a1 += f.y;
    }
    float inv = 1.0f / (float)max(e - s, 1);
    float2 sv = *reinterpret_cast<const float2*>(self + (size_t)node * 64 + lane * 2);
    *reinterpret_cast<float2*>(out + (size_t)node * 64 + lane * 2) =
        make_float2(sv.x + a0 * inv, sv.y + a1 * inv);
}

// ---------------- fp16 GEMM: 512 threads, 4x4 warp grid, 32 acc regs/thread ----------------
// MODE 0: relu*mask epilogue, fp16 128-wide output (layers 1,2)
// MODE 2: layer-3 split: cols<64 -> self fp32 (+bias), cols>=64 -> p16 fp16 (no bias)
template <int KCHUNKS, bool DUAL, int MODE>
__global__ void __launch_bounds__(512, 2)
sage_mma_kernel(const __half* __restrict__ A0, const __half* __restrict__ A1,
                const __half* __restrict__ B16,
                const float* __restrict__ bias, const float* __restrict__ mask,
                float* __restrict__ out, __half* __restrict__ h16out) {
    constexpr int PAD = 40;                 // halves per smem row (conflict-free ldmatrix)
    constexpr int KTOT = KCHUNKS * 32;
    constexpr int BUFH = 128 * PAD;
    extern __shared__ uint16_t sm[];
    const uint32_t base = smem_u32(sm);
    uint16_t* sA = sm;                      // [2][128][PAD]
    uint16_t* sB = sm + 2 * BUFH;           // [2][128][PAD]

    const int tid = threadIdx.x, lane = tid & 31, wid = tid >> 5;
    const int bm = blockIdx.x * 128;
    const int wm = (wid & 3) * 32;          // 4 warps down M (32 rows each)
    const int wn = (wid >> 2) * 32;         // 4 warps across N (32 cols each)

    float acc[2][4][4];                     // 32 regs: 2 m16-tiles x 4 n8-tiles
#pragma unroll
    for (int m = 0; m < 2; m++)
#pragma unroll
        for (int n = 0; n < 4; n++)
#pragma unroll
            for (int i = 0; i < 4; i++) acc[m][n][i] = 0.f;

    uint4 pa, pb;
    const int srow = tid >> 2, sq = tid & 3;   // staging: 1 uint4/thread
    auto loadAB = [&](int ch) {
        const __half* asrc = DUAL ? (ch < KCHUNKS / 2 ? A0 : A1) : A0;
        int klocal = DUAL ? (ch & (KCHUNKS / 2 - 1)) * 32 : ch * 32;
        int k0 = ch * 32;
        int grow = bm + srow;
        pa = (grow < NN)
            ? *reinterpret_cast<const uint4*>(asrc + (size_t)grow * 128 + klocal + sq * 8)
            : make_uint4(0, 0, 0, 0);
        pb = *reinterpret_cast<const uint4*>(B16 + srow * KTOT + k0 + sq * 8);
    };
    auto storeAB = [&](int buf) {
        int off = buf * BUFH + srow * PAD + sq * 8;
        *reinterpret_cast<uint4*>(&sA[off]) = pa;
        *reinterpret_cast<uint4*>(&sB[off]) = pb;
    };

    loadAB(0);
    storeAB(0);

    for (int ch = 0; ch < KCHUNKS; ch++) {
        __syncthreads();
        int buf = ch & 1;
        bool more = (ch + 1 < KCHUNKS);
        if (more) loadAB(ch + 1);

#pragma unroll
        for (int ks = 0; ks < 2; ks++) {
            uint32_t ah[2][4];
            int arow = wm + (lane & 7) + ((lane >> 3) & 1) * 8;
            int acol = ks * 16 + (lane >> 4) * 8;
#pragma unroll
            for (int m = 0; m < 2; m++) {
                uint32_t aoff = (uint32_t)(buf * BUFH + (arow + m * 16) * PAD + acol) * 2;
                ldsm_x4(ah[m], base + aoff);
            }
            int brow = wn + (lane & 7) + ((lane >> 4) & 1) * 8;
            int bcol = ks * 16 + ((lane >> 3) & 1) * 8;
#pragma unroll
            for (int nt2 = 0; nt2 < 2; nt2++) {
                uint32_t bh[4];
                uint32_t boff = (uint32_t)((2 + buf) * BUFH + (brow + nt2 * 16) * PAD + bcol) * 2;
                ldsm_x4(bh, base + boff);
#pragma unroll
                for (int m = 0; m < 2; m++) {
                    mma_f16(acc[m][nt2 * 2], ah[m], &bh[0]);
                    mma_f16(acc[m][nt2 * 2 + 1], ah[m], &bh[2]);
                }
            }
        }
        if (more) storeAB(buf ^ 1);
    }

    // ---- epilogue ----
#pragma unroll
    for (int m = 0; m < 2; m++) {
        int r0 = bm + wm + m * 16 + (lane >> 2);
#pragma unroll
        for (int nt = 0; nt < 4; nt++) {
            int c = wn + nt * 8 + (lane & 3) * 2;
#pragma unroll
            for (int hh = 0; hh < 2; hh++) {
                int r = r0 + hh * 8;
                if (r >= NN) continue;
                float v0 = acc[m][nt][hh * 2 + 0];
                float v1 = acc[m][nt][hh * 2 + 1];
                if (MODE == 0) {
                    v0 += bias[c];
                    v1 += bias[c + 1];
                    float2 mv = *reinterpret_cast<const float2*>(mask + (size_t)r * 128 + c);
                    v0 = fmaxf(v0, 0.f) * mv.x;
                    v1 = fmaxf(v1, 0.f) * mv.y;
                    *reinterpret_cast<__half2*>(h16out + (size_t)r * 128 + c) =
                        __floats2half2_rn(v0, v1);
                } else {
                    if (c < 64) {
                        v0 += bias[c];
                        v1 += bias[c + 1];
                        *reinterpret_cast<float2*>(out + (size_t)r * 64 + c) = make_float2(v0, v1);
                    } else {
                        *reinterpret_cast<__half2*>(h16out + (size_t)r * 64 + (c - 64)) =
                            __floats2half2_rn(v0, v1);
                    }
                }
            }
        }
    }
}

// ---------------- launch ----------------
extern "C" void kernel_launch(void* const* d_in, const int* in_sizes, int n_in,
                              void* d_out, int out_size) {
    const float* x   = (const float*)d_in[0];
    const int*   src = (const int*)d_in[1];
    const int*   dst = (const int*)d_in[2];
    const float* Ws1 = (const float*)d_in[3];
    const float* Wn1 = (const float*)d_in[4];
    const float* b1  = (const float*)d_in[5];
    const float* Ws2 = (const float*)d_in[6];
    const float* Wn2 = (const float*)d_in[7];
    const float* b2  = (const float*)d_in[8];
    const float* Ws3 = (const float*)d_in[9];
    const float* Wn3 = (const float*)d_in[10];
    const float* b3  = (const float*)d_in[11];
    const float* m1  = (const float*)d_in[12];
    const float* m2  = (const float*)d_in[13];
    float* out = (float*)d_out;

    // Real DEVICE addresses (host symbol = ATS shadow trap, see R1)
    __half *x16 = nullptr, *hA16 = nullptr, *hB16 = nullptr, *n16 = nullptr, *B16 = nullptr;
    float* selfp = nullptr;
    cudaGetSymbolAddress((void**)&x16, g_x16);
    cudaGetSymbolAddress((void**)&hA16, g_hA16);
    cudaGetSymbolAddress((void**)&hB16, g_hB16);
    cudaGetSymbolAddress((void**)&n16, g_n16);
    cudaGetSymbolAddress((void**)&B16, g_B16);
    cudaGetSymbolAddress((void**)&selfp, g_self);

    constexpr int SMEM_GEMM = 4 * 128 * 40 * 2;  // 40960 B
    cudaFuncSetAttribute(sage_mma_kernel<8, true, 0>,
                         cudaFuncAttributeMaxDynamicSharedMemorySize, SMEM_GEMM);
    cudaFuncSetAttribute(sage_mma_kernel<4, false, 2>,
                         cudaFuncAttributeMaxDynamicSharedMemorySize, SMEM_GEMM);

    // ---- setup (conv + weight prep + deg zero) ----
    setup_kernel<<<(NCONV4 + NWPREP + NDEG4 + 255) / 256, 256>>>(
        (const float4*)x, (uint2*)x16, Ws1, Wn1, Ws2, Wn2, Ws3, Wn3, B16);

    // ---- CSR build ----
    count4_kernel<<<(EE / 4 + 255) / 256, 256>>>((const int4*)dst);
    scan12_kernel<<<NBLK, 256>>>();
    scan_final<<<NBLK, 256>>>();
    fill4_kernel<<<(EE / 4 + 255) / 256, 256>>>((const int4*)src, (const int4*)dst);

    int aggBlocks = (NN * 32 + 255) / 256;

    // ---- layer 1 ----
    agg16_kernel<<<aggBlocks, 256>>>(x16, n16);
    sage_mma_kernel<8, true, 0><<<TILES, 512, SMEM_GEMM>>>(x16, n16, B16, b1, m1, nullptr, hA16);

    // ---- layer 2 ----
    agg16_kernel<<<aggBlocks, 256>>>(hA16, n16);
    sage_mma_kernel<8, true, 0><<<TILES, 512, SMEM_GEMM>>>(hA16, n16, B16 + 32768, b2, m2, nullptr, hB16);

    // ---- layer 3: project (self fp32, proj fp16 into x16), then aggregate ----
    sage_mma_kernel<4, false, 2><<<TILES, 512, SMEM_GEMM>>>(hB16, nullptr, B16 + 65536, b3, nullptr, selfp, x16);
    agg3_kernel<<<aggBlocks, 256>>>(x16, selfp, out);
}

// round 16
// speedup vs baseline: 1.0974x; 1.0634x over previous
#include <cuda_runtime.h>
#include <cuda_fp16.h>
#include <cstdint>

#define NN 50000
#define EE 800000
#define NBLK 196   // ceil(NN/256)
#define TILES 391  // ceil(NN/128)

// ---------------- device scratch (all-fp16 activation pipeline) ----------------
__device__ __half g_x16[NN * 128];    // x mirror; reused as layer-3 proj p16 [NN*64]
__device__ __half g_hA16[NN * 128];   // layer-1 activations
__device__ __half g_hB16[NN * 128];   // layer-2 activations
__device__ __half g_n16[NN * 128];    // aggregated neighbor features
__device__ float  g_self[NN * 64];    // layer-3 self projection (fp32)
__device__ int   g_deg[NN];
__device__ int   g_off[NN + 1];
__device__ int   g_cur[NN];
__device__ int   g_csr[EE];
__device__ int   g_bsum[256];
__device__ int   g_boff[256];
__device__ int   g_scanctr;
__device__ __half g_B16[3 * 128 * 256]; // transposed fp16 weights, 3 layers

// ---------------- helpers ----------------
__device__ __forceinline__ uint32_t smem_u32(const void* p) {
    uint32_t a;
    asm("{ .reg .u64 t; cvta.to.shared.u64 t, %1; cvt.u32.u64 %0, t; }" : "=r"(a) : "l"(p));
    return a;
}
__device__ __forceinline__ void mma_f16(float* d, const uint32_t* a, const uint32_t* b) {
    asm volatile(
        "mma.sync.aligned.m16n8k16.row.col.f32.f16.f16.f32 "
        "{%0,%1,%2,%3}, {%4,%5,%6,%7}, {%8,%9}, {%0,%1,%2,%3};"
        : "+f"(d[0]), "+f"(d[1]), "+f"(d[2]), "+f"(d[3])
        : "r"(a[0]), "r"(a[1]), "r"(a[2]), "r"(a[3]), "r"(b[0]), "r"(b[1]));
}
__device__ __forceinline__ void ldsm_x4(uint32_t* r, uint32_t addr) {
    asm volatile("ldmatrix.sync.aligned.m8n8.x4.shared.b16 {%0,%1,%2,%3}, [%4];"
                 : "=r"(r[0]), "=r"(r[1]), "=r"(r[2]), "=r"(r[3]) : "r"(addr));
}
__device__ __forceinline__ void cp_async16(uint32_t saddr, const void* gaddr, int szbytes) {
    asm volatile("cp.async.cg.shared.global [%0], [%1], 16, %2;"
                 :: "r"(saddr), "l"(gaddr), "r"(szbytes));
}
__device__ __forceinline__ void cp_async16(uint32_t saddr, const void* gaddr) {
    asm volatile("cp.async.cg.shared.global [%0], [%1], 16;" :: "r"(saddr), "l"(gaddr));
}
#define CP_COMMIT() asm volatile("cp.async.commit_group;" ::: "memory")
template <int N>
__device__ __forceinline__ void cp_wait() {
    asm volatile("cp.async.wait_group %0;" :: "n"(N) : "memory");
}

// ---------------- setup: x conv + weight prep + deg zero ----------------
#define NCONV4 (NN * 32)
#define NWPREP (2 * 128 * 256 + 128 * 128)
#define NDEG4  (NN / 4)
__global__ void setup_kernel(const float4* __restrict__ x4, uint2* __restrict__ x16,
                             const float* __restrict__ Ws1, const float* __restrict__ Wn1,
                             const float* __restrict__ Ws2, const float* __restrict__ Wn2,
                             const float* __restrict__ Ws3, const float* __restrict__ Wn3,
                             __half* __restrict__ B16) {
    int idx = blockIdx.x * blockDim.x + threadIdx.x;
    if (idx < NCONV4) {
        float4 v = x4[idx];
        __half2 h0 = __floats2half2_rn(v.x, v.y);
        __half2 h1 = __floats2half2_rn(v.z, v.w);
        x16[idx] = make_uint2(*reinterpret_cast<uint32_t*>(&h0), *reinterpret_cast<uint32_t*>(&h1));
        return;
    }
    int w = idx - NCONV4;
    if (w < 2 * 128 * 256) {
        int layer = w >> 15;
        int li = w & 32767;
        int n = li >> 8, k = li & 255;
        const float* W1 = layer ? Ws2 : Ws1;
        const float* W2 = layer ? Wn2 : Wn1;
        float wv = (k < 128) ? W1[k * 128 + n] : W2[(k - 128) * 128 + n];
        B16[w] = __float2half_rn(wv);
    } else if (w < NWPREP) {
        int li = w - 2 * 128 * 256;
        int n = li >> 7, k = li & 127;
        float wv = (n < 64) ? Ws3[k * 64 + n] : Wn3[k * 64 + (n - 64)];
        B16[2 * 128 * 256 + n * 128 + k] = __float2half_rn(wv);
    } else if (w < NWPREP + NDEG4) {
        reinterpret_cast<int4*>(g_deg)[w - NWPREP] = make_int4(0, 0, 0, 0);
    }
}

// ---------------- CSR build ----------------
__global__ void count4_kernel(const int4* __restrict__ dst4) {
    int i = blockIdx.x * blockDim.x + threadIdx.x;
    if (i == 0) g_scanctr = 0;
    if (i < EE / 4) {
        int4 d = dst4[i];
        atomicAdd(&g_deg[d.x], 1);
        atomicAdd(&g_deg[d.y], 1);
        atomicAdd(&g_deg[d.z], 1);
        atomicAdd(&g_deg[d.w], 1);
    }
}
__global__ void scan12_kernel() {
    __shared__ int sh[256];
    __shared__ int lastflag;
    int t = threadIdx.x;
    int i = blockIdx.x * 256 + t;
    sh[t] = (i < NN) ? g_deg[i] : 0;
    __syncthreads();
    for (int o = 128; o > 0; o >>= 1) {
        if (t < o) sh[t] += sh[t + o];
        __syncthreads();
    }
    if (t == 0) {
        g_bsum[blockIdx.x] = sh[0];
        __threadfence();
        lastflag = (atomicAdd(&g_scanctr, 1) == NBLK - 1);
    }
    __syncthreads();
    if (lastflag) {
        int v = (t < NBLK) ? g_bsum[t] : 0;
        sh[t] = v;
        __syncthreads();
        for (int o = 1; o < 256; o <<= 1) {
            int x = (t >= o) ? sh[t - o] : 0;
            __syncthreads();
            sh[t] += x;
            __syncthreads();
        }
        if (t < NBLK) g_boff[t] = sh[t] - v;   // exclusive
    }
}
__global__ void scan_final() {
    __shared__ int sh[256];
    int t = threadIdx.x;
    int i = blockIdx.x * 256 + t;
    int v = (i < NN) ? g_deg[i] : 0;
    sh[t] = v;
    __syncthreads();
    for (int o = 1; o < 256; o <<= 1) {
        int x = (t >= o) ? sh[t - o] : 0;
        __syncthreads();
        sh[t] += x;
        __syncthreads();
    }
    int off = g_boff[blockIdx.x] + sh[t] - v;   // exclusive
    if (i <= NN) g_off[i] = off;
    if (i < NN) g_cur[i] = off;
}
__global__ void fill4_kernel(const int4* __restrict__ src4, const int4* __restrict__ dst4) {
    int i = blockIdx.x * blockDim.x + threadIdx.x;
    if (i < EE / 4) {
        int4 d = dst4[i];
        int4 s = src4[i];
        int p0 = atomicAdd(&g_cur[d.x], 1);
        int p1 = atomicAdd(&g_cur[d.y], 1);
        int p2 = atomicAdd(&g_cur[d.z], 1);
        int p3 = atomicAdd(&g_cur[d.w], 1);
        g_csr[p0] = s.x;
        g_csr[p1] = s.y;
        g_csr[p2] = s.z;
        g_csr[p3] = s.w;
    }
}

// ---------------- mean aggregation (128-dim): warp per node, fp16 in/out ----------------
__global__ void agg16_kernel(const __half* __restrict__ h16, __half* __restrict__ n16) {
    int gt = blockIdx.x * blockDim.x + threadIdx.x;
    int node = gt >> 5;
    int lane = gt & 31;
    if (node >= NN) return;
    int s = g_off[node], e = g_off[node + 1];
    float a0 = 0.f, a1 = 0.f, a2 = 0.f, a3 = 0.f;
    int j = s;
    for (; j + 4 <= e; j += 4) {
        int i0 = g_csr[j], i1 = g_csr[j + 1], i2 = g_csr[j + 2], i3 = g_csr[j + 3];
        uint2 v0 = *reinterpret_cast<const uint2*>(h16 + (size_t)i0 * 128 + lane * 4);
        uint2 v1 = *reinterpret_cast<const uint2*>(h16 + (size_t)i1 * 128 + lane * 4);
        uint2 v2 = *reinterpret_cast<const uint2*>(h16 + (size_t)i2 * 128 + lane * 4);
        uint2 v3 = *reinterpret_cast<const uint2*>(h16 + (size_t)i3 * 128 + lane * 4);
        float2 f;
        f = __half22float2(*reinterpret_cast<__half2*>(&v0.x)); a0 += f.x; a1 += f.y;
        f = __half22float2(*reinterpret_cast<__half2*>(&v0.y)); a2 += f.x; a3 += f.y;
        f = __half22float2(*reinterpret_cast<__half2*>(&v1.x)); a0 += f.x; a1 += f.y;
        f = __half22float2(*reinterpret_cast<__half2*>(&v1.y)); a2 += f.x; a3 += f.y;
        f = __half22float2(*reinterpret_cast<__half2*>(&v2.x)); a0 += f.x; a1 += f.y;
        f = __half22float2(*reinterpret_cast<__half2*>(&v2.y)); a2 += f.x; a3 += f.y;
        f = __half22float2(*reinterpret_cast<__half2*>(&v3.x)); a0 += f.x; a1 += f.y;
        f = __half22float2(*reinterpret_cast<__half2*>(&v3.y)); a2 += f.x; a3 += f.y;
    }
    for (; j < e; j++) {
        int sidx = g_csr[j];
        uint2 v = *reinterpret_cast<const uint2*>(h16 + (size_t)sidx * 128 + lane * 4);
        float2 f0 = __half22float2(*reinterpret_cast<__half2*>(&v.x));
        float2 f1 = __half22float2(*reinterpret_cast<__half2*>(&v.y));
        a0 += f0.x; a1 += f0.y; a2 += f1.x; a3 += f1.y;
    }
    float inv = 1.0f / (float)max(e - s, 1);
    __half2 o0 = __floats2half2_rn(a0 * inv, a1 * inv);
    __half2 o1 = __floats2half2_rn(a2 * inv, a3 * inv);
    *reinterpret_cast<uint2*>(n16 + (size_t)node * 128 + lane * 4) =
        make_uint2(*reinterpret_cast<uint32_t*>(&o0), *reinterpret_cast<uint32_t*>(&o1));
}

// ---------------- layer-3 final: out = self + mean(proj16[src]) ----------------
__global__ void agg3_kernel(const __half* __restrict__ p16, const float* __restrict__ self,
                            float* __restrict__ out) {
    int gt = blockIdx.x * blockDim.x + threadIdx.x;
    int node = gt >> 5;
    int lane = gt & 31;
    if (node >= NN) return;
    int s = g_off[node], e = g_off[node + 1];
    float a0 = 0.f, a1 = 0.f;
    int j = s;
    for (; j + 4 <= e; j += 4) {
        int i0 = g_csr[j], i1 = g_csr[j + 1], i2 = g_csr[j + 2], i3 = g_csr[j + 3];
        uint32_t v0 = *reinterpret_cast<const uint32_t*>(p16 + (size_t)i0 * 64 + lane * 2);
        uint32_t v1 = *reinterpret_cast<const uint32_t*>(p16 + (size_t)i1 * 64 + lane * 2);
        uint32_t v2 = *reinterpret_cast<const uint32_t*>(p16 + (size_t)i2 * 64 + lane * 2);
        uint32_t v3 = *reinterpret_cast<const uint32_t*>(p16 + (size_t)i3 * 64 + lane * 2);
        float2 f;
        f = __half22float2(*reinterpret_cast<__half2*>(&v0)); a0 += f.x; a1 += f.y;
        f = __half22float2(*reinterpret_cast<__half2*>(&v1)); a0 += f.x; a1 += f.y;
        f = __half22float2(*reinterpret_cast<__half2*>(&v2)); a0 += f.x; a1 += f.y;
        f = __half22float2(*reinterpret_cast<__half2*>(&v3)); a0 += f.x; a1 += f.y;
    }
    for (; j < e; j++) {
        int sidx = g_csr[j];
        uint32_t v = *reinterpret_cast<const uint32_t*>(p16 + (size_t)sidx * 64 + lane * 2);
        float2 f = __half22float2(*reinterpret_cast<__half2*>(&v));
        a0 += f.x; a1 += f.y;
    }
    float inv = 1.0f / (float)max(e - s, 1);
    float2 sv = *reinterpret_cast<const float2*>(self + (size_t)node * 64 + lane * 2);
    *reinterpret_cast<float2*>(out + (size_t)node * 64 + lane * 2) =
        make_float2(sv.x + a0 * inv, sv.y + a1 * inv);
}

// ---------------- fp16 GEMM: 256 threads, cp.async 3-stage pipeline ----------------
// MODE 0: relu*mask epilogue, fp16 128-wide output (layers 1,2)
// MODE 2: layer-3 split: cols<64 -> self fp32 (+bias), cols>=64 -> p16 fp16 (no bias)
template <int KCHUNKS, bool DUAL, int MODE>
__global__ void __launch_bounds__(256, 2)
sage_mma_kernel(const __half* __restrict__ A0, const __half* __restrict__ A1,
                const __half* __restrict__ B16,
                const float* __restrict__ bias, const float* __restrict__ mask,
                float* __restrict__ out, __half* __restrict__ h16out) {
    constexpr int PAD = 40;                 // halves per smem row (conflict-free ldmatrix)
    constexpr int KTOT = KCHUNKS * 32;
    constexpr int BUFH = 128 * PAD;         // halves per matrix per stage
    constexpr int STAGEH = 2 * BUFH;        // A + B per stage
    extern __shared__ uint16_t sm[];
    const uint32_t base = smem_u32(sm);

    const int tid = threadIdx.x, lane = tid & 31, wid = tid >> 5;
    const int bm = blockIdx.x * 128;
    const int wm = (wid & 3) * 32;          // 4 warps down M
    const int wn = (wid >> 2) * 64;         // 2 warps across N

    float acc[2][8][4];
#pragma unroll
    for (int m = 0; m < 2; m++)
#pragma unroll
        for (int n = 0; n < 8; n++)
#pragma unroll
            for (int i = 0; i < 4; i++) acc[m][n][i] = 0.f;

    // staging: 2 items/thread for A, 2 for B (each 16B), direct GMEM->SMEM
    auto issue = [&](int ch, int stage) {
        const __half* asrc = DUAL ? (ch < KCHUNKS / 2 ? A0 : A1) : A0;
        int klocal = DUAL ? (ch & (KCHUNKS / 2 - 1)) * 32 : ch * 32;
        int k0 = ch * 32;
        uint32_t sbase = base + (uint32_t)(stage * STAGEH) * 2;
#pragma unroll
        for (int j = 0; j < 2; j++) {
            int item = tid + j * 256;
            int row = item >> 2, q = item & 3;
            int grow = bm + row;
            int garow = (grow < NN) ? grow : (NN - 1);      // valid addr even when zfilled
            cp_async16(sbase + (uint32_t)(row * PAD + q * 8) * 2,
                       asrc + (size_t)garow * 128 + klocal + q * 8,
                       (grow < NN) ? 16 : 0);
            cp_async16(sbase + (uint32_t)(BUFH + row * PAD + q * 8) * 2,
                       B16 + row * KTOT + k0 + q * 8);
        }
        CP_COMMIT();
    };

    issue(0, 0);
    if (KCHUNKS > 1) issue(1, 1);

    for (int ch = 0; ch < KCHUNKS; ch++) {
        if (ch < KCHUNKS - 1) cp_wait<1>(); else cp_wait<0>();
        __syncthreads();
        int stage = ch % 3;
        uint32_t sbase = base + (uint32_t)(stage * STAGEH) * 2;

#pragma unroll
        for (int ks = 0; ks < 2; ks++) {
            uint32_t ah[2][4];
            int arow = wm + (lane & 7) + ((lane >> 3) & 1) * 8;
            int acol = ks * 16 + (lane >> 4) * 8;
#pragma unroll
            for (int m = 0; m < 2; m++) {
                ldsm_x4(ah[m], sbase + (uint32_t)((arow + m * 16) * PAD + acol) * 2);
            }
            int brow = wn + (lane & 7) + ((lane >> 4) & 1) * 8;
            int bcol = ks * 16 + ((lane >> 3) & 1) * 8;
#pragma unroll
            for (int nt2 = 0; nt2 < 4; nt2++) {
                uint32_t bh[4];
                ldsm_x4(bh, sbase + (uint32_t)(BUFH + (brow + nt2 * 16) * PAD + bcol) * 2);
#pragma unroll
                for (int m = 0; m < 2; m++) {
                    mma_f16(acc[m][nt2 * 2], ah[m], &bh[0]);
                    mma_f16(acc[m][nt2 * 2 + 1], ah[m], &bh[2]);
                }
            }
        }
        if (ch + 2 < KCHUNKS) issue(ch + 2, (ch + 2) % 3);
    }

    // ---- epilogue ----
#pragma unroll
    for (int m = 0; m < 2; m++) {
        int r0 = bm + wm + m * 16 + (lane >> 2);
#pragma unroll
        for (int nt = 0; nt < 8; nt++) {
            int c = wn + nt * 8 + (lane & 3) * 2;
#pragma unroll
            for (int hh = 0; hh < 2; hh++) {
                int r = r0 + hh * 8;
                if (r >= NN) continue;
                float v0 = acc[m][nt][hh * 2 + 0];
                float v1 = acc[m][nt][hh * 2 + 1];
                if (MODE == 0) {
                    v0 += bias[c];
                    v1 += bias[c + 1];
                    float2 mv = *reinterpret_cast<const float2*>(mask + (size_t)r * 128 + c);
                    v0 = fmaxf(v0, 0.f) * mv.x;
                    v1 = fmaxf(v1, 0.f) * mv.y;
                    *reinterpret_cast<__half2*>(h16out + (size_t)r * 128 + c) =
                        __floats2half2_rn(v0, v1);
                } else {
                    if (c < 64) {
                        v0 += bias[c];
                        v1 += bias[c + 1];
                        *reinterpret_cast<float2*>(out + (size_t)r * 64 + c) = make_float2(v0, v1);
                    } else {
                        *reinterpret_cast<__half2*>(h16out + (size_t)r * 64 + (c - 64)) =
                            __floats2half2_rn(v0, v1);
                    }
                }
            }
        }
    }
}

// ---------------- launch ----------------
extern "C" void kernel_launch(void* const* d_in, const int* in_sizes, int n_in,
                              void* d_out, int out_size) {
    const float* x   = (const float*)d_in[0];
    const int*   src = (const int*)d_in[1];
    const int*   dst = (const int*)d_in[2];
    const float* Ws1 = (const float*)d_in[3];
    const float* Wn1 = (const float*)d_in[4];
    const float* b1  = (const float*)d_in[5];
    const float* Ws2 = (const float*)d_in[6];
    const float* Wn2 = (const float*)d_in[7];
    const float* b2  = (const float*)d_in[8];
    const float* Ws3 = (const float*)d_in[9];
    const float* Wn3 = (const float*)d_in[10];
    const float* b3  = (const float*)d_in[11];
    const float* m1  = (const float*)d_in[12];
    const float* m2  = (const float*)d_in[13];
    float* out = (float*)d_out;

    // Real DEVICE addresses (host symbol = ATS shadow trap, see R1)
    __half *x16 = nullptr, *hA16 = nullptr, *hB16 = nullptr, *n16 = nullptr, *B16 = nullptr;
    float* selfp = nullptr;
    cudaGetSymbolAddress((void**)&x16, g_x16);
    cudaGetSymbolAddress((void**)&hA16, g_hA16);
    cudaGetSymbolAddress((void**)&hB16, g_hB16);
    cudaGetSymbolAddress((void**)&n16, g_n16);
    cudaGetSymbolAddress((void**)&B16, g_B16);
    cudaGetSymbolAddress((void**)&selfp, g_self);

    constexpr int SMEM_GEMM = 3 * 2 * 128 * 40 * 2;  // 61440 B (3 stages x (A+B))
    cudaFuncSetAttribute(sage_mma_kernel<8, true, 0>,
                         cudaFuncAttributeMaxDynamicSharedMemorySize, SMEM_GEMM);
    cudaFuncSetAttribute(sage_mma_kernel<4, false, 2>,
                         cudaFuncAttributeMaxDynamicSharedMemorySize, SMEM_GEMM);

    // ---- setup (conv + weight prep + deg zero) ----
    setup_kernel<<<(NCONV4 + NWPREP + NDEG4 + 255) / 256, 256>>>(
        (const float4*)x, (uint2*)x16, Ws1, Wn1, Ws2, Wn2, Ws3, Wn3, B16);

    // ---- CSR build ----
    count4_kernel<<<(EE / 4 + 255) / 256, 256>>>((const int4*)dst);
    scan12_kernel<<<NBLK, 256>>>();
    scan_final<<<NBLK, 256>>>();
    fill4_kernel<<<(EE / 4 + 255) / 256, 256>>>((const int4*)src, (const int4*)dst);

    int aggBlocks = (NN * 32 + 255) / 256;

    // ---- layer 1 ----
    agg16_kernel<<<aggBlocks, 256>>>(x16, n16);
    sage_mma_kernel<8, true, 0><<<TILES, 256, SMEM_GEMM>>>(x16, n16, B16, b1, m1, nullptr, hA16);

    // ---- layer 2 ----
    agg16_kernel<<<aggBlocks, 256>>>(hA16, n16);
    sage_mma_kernel<8, true, 0><<<TILES, 256, SMEM_GEMM>>>(hA16, n16, B16 + 32768, b2, m2, nullptr, hB16);

    // ---- layer 3: project (self fp32, proj fp16 into x16), then aggregate ----
    sage_mma_kernel<4, false, 2><<<TILES, 256, SMEM_GEMM>>>(hB16, nullptr, B16 + 65536, b3, nullptr, selfp, x16);
    agg3_kernel<<<aggBlocks, 256>>>(x16, selfp, out);
}

// round 17
// speedup vs baseline: 1.1028x; 1.0049x over previous
#include <cuda_runtime.h>
#include <cuda_fp16.h>
#include <cstdint>

#define NN 50000
#define EE 800000
#define NBLK 196   // ceil(NN/256)
#define TILES 391  // ceil(NN/128)

// ---------------- device scratch (all-fp16 activation pipeline) ----------------
__device__ __half g_x16[NN * 128];    // x mirror; reused as layer-3 proj p16 [NN*64]
__device__ __half g_hA16[NN * 128];   // layer-1 activations
__device__ __half g_hB16[NN * 128];   // layer-2 activations
__device__ __half g_n16[NN * 128];    // aggregated neighbor features
__device__ float  g_self[NN * 64];    // layer-3 self projection (fp32)
__device__ int   g_deg[NN];           // ZERO at entry of every launch (see scan_final)
__device__ int   g_off[NN + 1];
__device__ int   g_cur[NN];
__device__ int   g_csr[EE];
__device__ int   g_bsum[256];
__device__ int   g_boff[256];
__device__ int   g_scanctr;
__device__ __half g_B16[3 * 128 * 256]; // transposed fp16 weights, 3 layers

// ---------------- helpers ----------------
__device__ __forceinline__ uint32_t smem_u32(const void* p) {
    uint32_t a;
    asm("{ .reg .u64 t; cvta.to.shared.u64 t, %1; cvt.u32.u64 %0, t; }" : "=r"(a) : "l"(p));
    return a;
}
__device__ __forceinline__ void mma_f16(float* d, const uint32_t* a, const uint32_t* b) {
    asm volatile(
        "mma.sync.aligned.m16n8k16.row.col.f32.f16.f16.f32 "
        "{%0,%1,%2,%3}, {%4,%5,%6,%7}, {%8,%9}, {%0,%1,%2,%3};"
        : "+f"(d[0]), "+f"(d[1]), "+f"(d[2]), "+f"(d[3])
        : "r"(a[0]), "r"(a[1]), "r"(a[2]), "r"(a[3]), "r"(b[0]), "r"(b[1]));
}
__device__ __forceinline__ void ldsm_x4(uint32_t* r, uint32_t addr) {
    asm volatile("ldmatrix.sync.aligned.m8n8.x4.shared.b16 {%0,%1,%2,%3}, [%4];"
                 : "=r"(r[0]), "=r"(r[1]), "=r"(r[2]), "=r"(r[3]) : "r"(addr));
}
__device__ __forceinline__ void cp_async16(uint32_t saddr, const void* gaddr, int szbytes) {
    asm volatile("cp.async.cg.shared.global [%0], [%1], 16, %2;"
                 :: "r"(saddr), "l"(gaddr), "r"(szbytes));
}
__device__ __forceinline__ void cp_async16(uint32_t saddr, const void* gaddr) {
    asm volatile("cp.async.cg.shared.global [%0], [%1], 16;" :: "r"(saddr), "l"(gaddr));
}
#define CP_COMMIT() asm volatile("cp.async.commit_group;" ::: "memory")
template <int N>
__device__ __forceinline__ void cp_wait() {
    asm volatile("cp.async.wait_group %0;" :: "n"(N) : "memory");
}

// ---------------- setup: x conv + weight prep + degree count (g_deg pre-zeroed) ----------------
#define NCONV4 (NN * 32)
#define NWPREP (2 * 128 * 256 + 128 * 128)
__global__ void setup_kernel(const float4* __restrict__ x4, uint2* __restrict__ x16,
                             const float* __restrict__ Ws1, const float* __restrict__ Wn1,
                             const float* __restrict__ Ws2, const float* __restrict__ Wn2,
                             const float* __restrict__ Ws3, const float* __restrict__ Wn3,
                             __half* __restrict__ B16, const int4* __restrict__ dst4) {
    int idx = blockIdx.x * blockDim.x + threadIdx.x;
    if (idx == 0) g_scanctr = 0;
    if (idx < NCONV4) {
        float4 v = x4[idx];
        __half2 h0 = __floats2half2_rn(v.x, v.y);
        __half2 h1 = __floats2half2_rn(v.z, v.w);
        x16[idx] = make_uint2(*reinterpret_cast<uint32_t*>(&h0), *reinterpret_cast<uint32_t*>(&h1));
        return;
    }
    int w = idx - NCONV4;
    if (w < 2 * 128 * 256) {
        int layer = w >> 15;
        int li = w & 32767;
        int n = li >> 8, k = li & 255;
        const float* W1 = layer ? Ws2 : Ws1;
        const float* W2 = layer ? Wn2 : Wn1;
        float wv = (k < 128) ? W1[k * 128 + n] : W2[(k - 128) * 128 + n];
        B16[w] = __float2half_rn(wv);
    } else if (w < NWPREP) {
        int li = w - 2 * 128 * 256;
        int n = li >> 7, k = li & 127;
        float wv = (n < 64) ? Ws3[k * 64 + n] : Wn3[k * 64 + (n - 64)];
        B16[2 * 128 * 256 + n * 128 + k] = __float2half_rn(wv);
    } else if (w < NWPREP + EE / 4) {
        // degree count; g_deg is zero here: zero-initialized at load, and
        // re-zeroed by scan_final at the end of every previous launch.
        int4 d = dst4[w - NWPREP];
        atomicAdd(&g_deg[d.x], 1);
        atomicAdd(&g_deg[d.y], 1);
        atomicAdd(&g_deg[d.z], 1);
        atomicAdd(&g_deg[d.w], 1);
    }
}

// ---------------- CSR build ----------------
__global__ void scan12_kernel() {
    __shared__ int sh[256];
    __shared__ int lastflag;
    int t = threadIdx.x;
    int i = blockIdx.x * 256 + t;
    sh[t] = (i < NN) ? g_deg[i] : 0;
    __syncthreads();
    for (int o = 128; o > 0; o >>= 1) {
        if (t < o) sh[t] += sh[t + o];
        __syncthreads();
    }
    if (t == 0) {
        g_bsum[blockIdx.x] = sh[0];
        __threadfence();
        lastflag = (atomicAdd(&g_scanctr, 1) == NBLK - 1);
    }
    __syncthreads();
    if (lastflag) {
        int v = (t < NBLK) ? g_bsum[t] : 0;
        sh[t] = v;
        __syncthreads();
        for (int o = 1; o < 256; o <<= 1) {
            int x = (t >= o) ? sh[t - o] : 0;
            __syncthreads();
            sh[t] += x;
            __syncthreads();
        }
        if (t < NBLK) g_boff[t] = sh[t] - v;   // exclusive
    }
}
__global__ void scan_final() {
    __shared__ int sh[256];
    int t = threadIdx.x;
    int i = blockIdx.x * 256 + t;
    int v = (i < NN) ? g_deg[i] : 0;
    sh[t] = v;
    __syncthreads();
    for (int o = 1; o < 256; o <<= 1) {
        int x = (t >= o) ? sh[t - o] : 0;
        __syncthreads();
        sh[t] += x;
        __syncthreads();
    }
    int off = g_boff[blockIdx.x] + sh[t] - v;   // exclusive
    if (i <= NN) g_off[i] = off;
    if (i < NN) {
        g_cur[i] = off;
        g_deg[i] = 0;     // leave g_deg zeroed for the NEXT launch's setup count
    }
}
__global__ void fill4_kernel(const int4* __restrict__ src4, const int4* __restrict__ dst4) {
    int i = blockIdx.x * blockDim.x + threadIdx.x;
    if (i < EE / 4) {
        int4 d = dst4[i];
        int4 s = src4[i];
        int p0 = atomicAdd(&g_cur[d.x], 1);
        int p1 = atomicAdd(&g_cur[d.y], 1);
        int p2 = atomicAdd(&g_cur[d.z], 1);
        int p3 = atomicAdd(&g_cur[d.w], 1);
        g_csr[p0] = s.x;
        g_csr[p1] = s.y;
        g_csr[p2] = s.z;
        g_csr[p3] = s.w;
    }
}

// ---------------- mean aggregation (128-dim): warp per node, fp16 in/out ----------------
__global__ void agg16_kernel(const __half* __restrict__ h16, __half* __restrict__ n16) {
    int gt = blockIdx.x * blockDim.x + threadIdx.x;
    int node = gt >> 5;
    int lane = gt & 31;
    if (node >= NN) return;
    int s = g_off[node], e = g_off[node + 1];
    float a0 = 0.f, a1 = 0.f, a2 = 0.f, a3 = 0.f;
    int j = s;
    for (; j + 4 <= e; j += 4) {
        int i0 = g_csr[j], i1 = g_csr[j + 1], i2 = g_csr[j + 2], i3 = g_csr[j + 3];
        uint2 v0 = *reinterpret_cast<const uint2*>(h16 + (size_t)i0 * 128 + lane * 4);
        uint2 v1 = *reinterpret_cast<const uint2*>(h16 + (size_t)i1 * 128 + lane * 4);
        uint2 v2 = *reinterpret_cast<const uint2*>(h16 + (size_t)i2 * 128 + lane * 4);
        uint2 v3 = *reinterpret_cast<const uint2*>(h16 + (size_t)i3 * 128 + lane * 4);
        float2 f;
        f = __half22float2(*reinterpret_cast<__half2*>(&v0.x)); a0 += f.x; a1 += f.y;
        f = __half22float2(*reinterpret_cast<__half2*>(&v0.y)); a2 += f.x; a3 += f.y;
        f = __half22float2(*reinterpret_cast<__half2*>(&v1.x)); a0 += f.x; a1 += f.y;
        f = __half22float2(*reinterpret_cast<__half2*>(&v1.y)); a2 += f.x; a3 += f.y;
        f = __half22float2(*reinterpret_cast<__half2*>(&v2.x)); a0 += f.x; a1 += f.y;
        f = __half22float2(*reinterpret_cast<__half2*>(&v2.y)); a2 += f.x; a3 += f.y;
        f = __half22float2(*reinterpret_cast<__half2*>(&v3.x)); a0 += f.x; a1 += f.y;
        f = __half22float2(*reinterpret_cast<__half2*>(&v3.y)); a2 += f.x; a3 += f.y;
    }
    for (; j < e; j++) {
        int sidx = g_csr[j];
        uint2 v = *reinterpret_cast<const uint2*>(h16 + (size_t)sidx * 128 + lane * 4);
        float2 f0 = __half22float2(*reinterpret_cast<__half2*>(&v.x));
        float2 f1 = __half22float2(*reinterpret_cast<__half2*>(&v.y));
        a0 += f0.x; a1 += f0.y; a2 += f1.x; a3 += f1.y;
    }
    float inv = 1.0f / (float)max(e - s, 1);
    __half2 o0 = __floats2half2_rn(a0 * inv, a1 * inv);
    __half2 o1 = __floats2half2_rn(a2 * inv, a3 * inv);
    *reinterpret_cast<uint2*>(n16 + (size_t)node * 128 + lane * 4) =
        make_uint2(*reinterpret_cast<uint32_t*>(&o0), *reinterpret_cast<uint32_t*>(&o1));
}

// ---------------- layer-3 final: out = self + mean(proj16[src]) ----------------
__global__ void agg3_kernel(const __half* __restrict__ p16, const float* __restrict__ self,
                            float* __restrict__ out) {
    int gt = blockIdx.x * blockDim.x + threadIdx.x;
    int node = gt >> 5;
    int lane = gt & 31;
    if (node >= NN) return;
    int s = g_off[node], e = g_off[node + 1];
    float a0 = 0.f, a1 = 0.f;
    int j = s;
    for (; j + 4 <= e; j += 4) {
        int i0 = g_csr[j], i1 = g_csr[j + 1], i2 = g_csr[j + 2], i3 = g_csr[j + 3];
        uint32_t v0 = *reinterpret_cast<const uint32_t*>(p16 + (size_t)i0 * 64 + lane * 2);
        uint32_t v1 = *reinterpret_cast<const uint32_t*>(p16 + (size_t)i1 * 64 + lane * 2);
        uint32_t v2 = *reinterpret_cast<const uint32_t*>(p16 + (size_t)i2 * 64 + lane * 2);
        uint32_t v3 = *reinterpret_cast<const uint32_t*>(p16 + (size_t)i3 * 64 + lane * 2);
        float2 f;
        f = __half22float2(*reinterpret_cast<__half2*>(&v0)); a0 += f.x; a1 += f.y;
        f = __half22float2(*reinterpret_cast<__half2*>(&v1)); a0 += f.x; a1 += f.y;
        f = __half22float2(*reinterpret_cast<__half2*>(&v2)); a0 += f.x; a1 += f.y;
        f = __half22float2(*reinterpret_cast<__half2*>(&v3)); a0 += f.x; a1 += f.y;
    }
    for (; j < e; j++) {
        int sidx = g_csr[j];
        uint32_t v = *reinterpret_cast<const uint32_t*>(p16 + (size_t)sidx * 64 + lane * 2);
        float2 f = __half22float2(*reinterpret_cast<__half2*>(&v));
        a0 += f.x; a1 += f.y;
    }
    float inv = 1.0f / (float)max(e - s, 1);
    float2 sv = *reinterpret_cast<const float2*>(self + (size_t)node * 64 + lane * 2);
    *reinterpret_cast<float2*>(out + (size_t)node * 64 + lane * 2) =
        make_float2(sv.x + a0 * inv, sv.y + a1 * inv);
}

// ---------------- fp16 GEMM: 256 threads, cp.async 3-stage pipeline ----------------
// MODE 0: relu*mask epilogue, fp16 128-wide output (layers 1,2)
// MODE 2: layer-3 split: cols<64 -> self fp32 (+bias), cols>=64 -> p16 fp16 (no bias)
template <int KCHUNKS, bool DUAL, int MODE>
__global__ void __launch_bounds__(256, 2)
sage_mma_kernel(const __half* __restrict__ A0, const __half* __restrict__ A1,
                const __half* __restrict__ B16,
                const float* __restrict__ bias, const float* __restrict__ mask,
                float* __restrict__ out, __half* __restrict__ h16out) {
    constexpr int PAD = 40;                 // halves per smem row (conflict-free ldmatrix)
    constexpr int KTOT = KCHUNKS * 32;
    constexpr int BUFH = 128 * PAD;         // halves per matrix per stage
    constexpr int STAGEH = 2 * BUFH;        // A + B per stage
    extern __shared__ uint16_t sm[];
    const uint32_t base = smem_u32(sm);

    const int tid = threadIdx.x, lane = tid & 31, wid = tid >> 5;
    const int bm = blockIdx.x * 128;
    const int wm = (wid & 3) * 32;          // 4 warps down M
    const int wn = (wid >> 2) * 64;         // 2 warps across N

    float acc[2][8][4];
#pragma unroll
    for (int m = 0; m < 2; m++)
#pragma unroll
        for (int n = 0; n < 8; n++)
#pragma unroll
            for (int i = 0; i < 4; i++) acc[m][n][i] = 0.f;

    // staging: 2 items/thread for A, 2 for B (each 16B), direct GMEM->SMEM
    auto issue = [&](int ch, int stage) {
        const __half* asrc = DUAL ? (ch < KCHUNKS / 2 ? A0 : A1) : A0;
        int klocal = DUAL ? (ch & (KCHUNKS / 2 - 1)) * 32 : ch * 32;
        int k0 = ch * 32;
        uint32_t sbase = base + (uint32_t)(stage * STAGEH) * 2;
#pragma unroll
        for (int j = 0; j < 2; j++) {
            int item = tid + j * 256;
            int row = item >> 2, q = item & 3;
            int grow = bm + row;
            int garow = (grow < NN) ? grow : (NN - 1);      // valid addr even when zfilled
            cp_async16(sbase + (uint32_t)(row * PAD + q * 8) * 2,
                       asrc + (size_t)garow * 128 + klocal + q * 8,
                       (grow < NN) ? 16 : 0);
            cp_async16(sbase + (uint32_t)(BUFH + row * PAD + q * 8) * 2,
                       B16 + row * KTOT + k0 + q * 8);
        }
        CP_COMMIT();
    };

    issue(0, 0);
    if (KCHUNKS > 1) issue(1, 1);

    for (int ch = 0; ch < KCHUNKS; ch++) {
        if (ch < KCHUNKS - 1) cp_wait<1>(); else cp_wait<0>();
        __syncthreads();
        int stage = ch % 3;
        uint32_t sbase = base + (uint32_t)(stage * STAGEH) * 2;

#pragma unroll
        for (int ks = 0; ks < 2; ks++) {
            uint32_t ah[2][4];
            int arow = wm + (lane & 7) + ((lane >> 3) & 1) * 8;
            int acol = ks * 16 + (lane >> 4) * 8;
#pragma unroll
            for (int m = 0; m < 2; m++) {
                ldsm_x4(ah[m], sbase + (uint32_t)((arow + m * 16) * PAD + acol) * 2);
            }
            int brow = wn + (lane & 7) + ((lane >> 4) & 1) * 8;
            int bcol = ks * 16 + ((lane >> 3) & 1) * 8;
#pragma unroll
            for (int nt2 = 0; nt2 < 4; nt2++) {
                uint32_t bh[4];
                ldsm_x4(bh, sbase + (uint32_t)(BUFH + (brow + nt2 * 16) * PAD + bcol) * 2);
#pragma unroll
                for (int m = 0; m < 2; m++) {
                    mma_f16(acc[m][nt2 * 2], ah[m], &bh[0]);
                    mma_f16(acc[m][nt2 * 2 + 1], ah[m], &bh[2]);
                }
            }
        }
        if (ch + 2 < KCHUNKS) issue(ch + 2, (ch + 2) % 3);
    }

    // ---- epilogue ----
#pragma unroll
    for (int m = 0; m < 2; m++) {
        int r0 = bm + wm + m * 16 + (lane >> 2);
#pragma unroll
        for (int nt = 0; nt < 8; nt++) {
            int c = wn + nt * 8 + (lane & 3) * 2;
#pragma unroll
            for (int hh = 0; hh < 2; hh++) {
                int r = r0 + hh * 8;
                if (r >= NN) continue;
                float v0 = acc[m][nt][hh * 2 + 0];
                float v1 = acc[m][nt][hh * 2 + 1];
                if (MODE == 0) {
                    v0 += bias[c];
                    v1 += bias[c + 1];
                    float2 mv = *reinterpret_cast<const float2*>(mask + (size_t)r * 128 + c);
                    v0 = fmaxf(v0, 0.f) * mv.x;
                    v1 = fmaxf(v1, 0.f) * mv.y;
                    *reinterpret_cast<__half2*>(h16out + (size_t)r * 128 + c) =
                        __floats2half2_rn(v0, v1);
                } else {
                    if (c < 64) {
                        v0 += bias[c];
                        v1 += bias[c + 1];
                        *reinterpret_cast<float2*>(out + (size_t)r * 64 + c) = make_float2(v0, v1);
                    } else {
                        *reinterpret_cast<__half2*>(h16out + (size_t)r * 64 + (c - 64)) =
                            __floats2half2_rn(v0, v1);
                    }
                }
            }
        }
    }
}

// ---------------- launch ----------------
extern "C" void kernel_launch(void* const* d_in, const int* in_sizes, int n_in,
                              void* d_out, int out_size) {
    const float* x   = (const float*)d_in[0];
    const int*   src = (const int*)d_in[1];
    const int*   dst = (const int*)d_in[2];
    const float* Ws1 = (const float*)d_in[3];
    const float* Wn1 = (const float*)d_in[4];
    const float* b1  = (const float*)d_in[5];
    const float* Ws2 = (const float*)d_in[6];
    const float* Wn2 = (const float*)d_in[7];
    const float* b2  = (const float*)d_in[8];
    const float* Ws3 = (const float*)d_in[9];
    const float* Wn3 = (const float*)d_in[10];
    const float* b3  = (const float*)d_in[11];
    const float* m1  = (const float*)d_in[12];
    const float* m2  = (const float*)d_in[13];
    float* out = (float*)d_out;

    // Real DEVICE addresses (host symbol = ATS shadow trap, see R1)
    __half *x16 = nullptr, *hA16 = nullptr, *hB16 = nullptr, *n16 = nullptr, *B16 = nullptr;
    float* selfp = nullptr;
    cudaGetSymbolAddress((void**)&x16, g_x16);
    cudaGetSymbolAddress((void**)&hA16, g_hA16);
    cudaGetSymbolAddress((void**)&hB16, g_hB16);
    cudaGetSymbolAddress((void**)&n16, g_n16);
    cudaGetSymbolAddress((void**)&B16, g_B16);
    cudaGetSymbolAddress((void**)&selfp, g_self);

    constexpr int SMEM_GEMM = 3 * 2 * 128 * 40 * 2;  // 61440 B (3 stages x (A+B))
    cudaFuncSetAttribute(sage_mma_kernel<8, true, 0>,
                         cudaFuncAttributeMaxDynamicSharedMemorySize, SMEM_GEMM);
    cudaFuncSetAttribute(sage_mma_kernel<4, false, 2>,
                         cudaFuncAttributeMaxDynamicSharedMemorySize, SMEM_GEMM);

    // ---- setup: conv + weight prep + degree count (g_deg is pre-zeroed) ----
    setup_kernel<<<(NCONV4 + NWPREP + EE / 4 + 255) / 256, 256>>>(
        (const float4*)x, (uint2*)x16, Ws1, Wn1, Ws2, Wn2, Ws3, Wn3, B16,
        (const int4*)dst);

    // ---- CSR build (scan_final re-zeroes g_deg for next launch) ----
    scan12_kernel<<<NBLK, 256>>>();
    scan_final<<<NBLK, 256>>>();
    fill4_kernel<<<(EE / 4 + 255) / 256, 256>>>((const int4*)src, (const int4*)dst);

    int aggBlocks = (NN * 32 + 255) / 256;

    // ---- layer 1 ----
    agg16_kernel<<<aggBlocks, 256>>>(x16, n16);
    sage_mma_kernel<8, true, 0><<<TILES, 256, SMEM_GEMM>>>(x16, n16, B16, b1, m1, nullptr, hA16);

    // ---- layer 2 ----
    agg16_kernel<<<aggBlocks, 256>>>(hA16, n16);
    sage_mma_kernel<8, true, 0><<<TILES, 256, SMEM_GEMM>>>(hA16, n16, B16 + 32768, b2, m2, nullptr, hB16);

    // ---- layer 3: project (self fp32, proj fp16 into x16), then aggregate ----
    sage_mma_kernel<4, false, 2><<<TILES, 256, SMEM_GEMM>>>(hB16, nullptr, B16 + 65536, b3, nullptr, selfp, x16);
    agg3_kernel<<<aggBlocks, 256>>>(x16, selfp, out);
}